// round 5
// baseline (speedup 1.0000x reference)
#include <cuda_runtime.h>
#include <math.h>
#include <stdint.h>

// ---------------------------------------------------------------------------
// MicrostepKimiDeltaAttention — Round 1 baseline (all fp32, SIMT)
// B=2, T=1024, HID=2048, H=16, D=DV=128, R=4, CONV=4
// ---------------------------------------------------------------------------

#define H_    16
#define D_    128
#define DV_   128
#define R_    4
#define HID_  2048
#define T_    1024
#define B_MAX 2
#define KD_   (H_ * D_)        // 2048
#define KDR_  (KD_ * R_)       // 8192
#define VDR_  (H_ * DV_ * R_)  // 8192

// ------------------------- scratch (device globals) ------------------------
__device__ float g_qpre [B_MAX * T_ * KD_];
__device__ float g_kpre [B_MAX * T_ * KDR_];
__device__ float g_vpre [B_MAX * T_ * VDR_];
__device__ float g_bpre [B_MAX * T_ * H_ * R_];
__device__ float g_f1h  [B_MAX * T_ * 128];
__device__ float g_g1h  [B_MAX * T_ * 128];
__device__ float g_graw [B_MAX * T_ * KD_];
__device__ float g_gate [B_MAX * T_ * H_ * DV_];
__device__ float g_qb   [B_MAX * T_ * KD_];
__device__ float g_kb   [B_MAX * T_ * KDR_];
__device__ float g_vb   [B_MAX * T_ * VDR_];
__device__ float g_dec  [B_MAX * T_ * KD_];
__device__ float g_beta [B_MAX * T_ * H_ * R_];
__device__ float g_omix [B_MAX * T_ * H_ * DV_];
__device__ float g_ofin [B_MAX * T_ * H_ * DV_];

static __device__ __forceinline__ float sigmoidf_(float x) { return 1.f / (1.f + expf(-x)); }
static __device__ __forceinline__ float softplusf_(float x) { return (x > 20.f) ? x : log1pf(expf(x)); }

// --------------------- GEMM: C[m,n] = sum_k A[m,k]*W[n,k] ------------------
#define GBM 128
#define GBN 128
#define GBK 8

__global__ void gemm_nt_kernel(const float* __restrict__ A, const float* __restrict__ W,
                               float* __restrict__ C, const float* __restrict__ bias,
                               int M, int N, int K)
{
    __shared__ float As[GBK][GBM];
    __shared__ float Ws[GBK][GBN];
    const int bm = blockIdx.y * GBM;
    const int bn = blockIdx.x * GBN;
    const int tid = threadIdx.x;          // 0..255
    const int tx = tid & 15;
    const int ty = tid >> 4;
    const int lrow = tid >> 1;            // 0..127
    const int lcol = (tid & 1) << 2;      // 0 or 4

    float acc[8][8];
#pragma unroll
    for (int i = 0; i < 8; i++)
#pragma unroll
        for (int j = 0; j < 8; j++) acc[i][j] = 0.f;

    for (int k0 = 0; k0 < K; k0 += GBK) {
        float4 av = make_float4(0.f, 0.f, 0.f, 0.f);
        float4 wv = make_float4(0.f, 0.f, 0.f, 0.f);
        int gm = bm + lrow;
        if (gm < M) av = *reinterpret_cast<const float4*>(A + (size_t)gm * K + k0 + lcol);
        int gn = bn + lrow;
        if (gn < N) wv = *reinterpret_cast<const float4*>(W + (size_t)gn * K + k0 + lcol);
        As[lcol + 0][lrow] = av.x; As[lcol + 1][lrow] = av.y;
        As[lcol + 2][lrow] = av.z; As[lcol + 3][lrow] = av.w;
        Ws[lcol + 0][lrow] = wv.x; Ws[lcol + 1][lrow] = wv.y;
        Ws[lcol + 2][lrow] = wv.z; Ws[lcol + 3][lrow] = wv.w;
        __syncthreads();
#pragma unroll
        for (int kk = 0; kk < GBK; kk++) {
            float ra[8], rb[8];
#pragma unroll
            for (int i = 0; i < 8; i++) ra[i] = As[kk][ty * 8 + i];
#pragma unroll
            for (int j = 0; j < 8; j++) rb[j] = Ws[kk][tx * 8 + j];
#pragma unroll
            for (int i = 0; i < 8; i++)
#pragma unroll
                for (int j = 0; j < 8; j++) acc[i][j] = fmaf(ra[i], rb[j], acc[i][j]);
        }
        __syncthreads();
    }
#pragma unroll
    for (int i = 0; i < 8; i++) {
        int gm = bm + ty * 8 + i;
        if (gm >= M) continue;
#pragma unroll
        for (int j = 0; j < 8; j++) {
            int gn = bn + tx * 8 + j;
            if (gn < N) {
                float v = acc[i][j];
                if (bias) v += bias[gn];
                C[(size_t)gm * N + gn] = v;
            }
        }
    }
}

// ------------------------- causal short conv + SiLU ------------------------
__global__ void conv_silu_kernel(const float* __restrict__ in, const float* __restrict__ w,
                                 float* __restrict__ out, int C, long total, int T)
{
    long idx = (long)blockIdx.x * blockDim.x + threadIdx.x;
    if (idx >= total) return;
    int c = (int)(idx % C);
    long bt = idx / C;
    int t = (int)(bt % T);
    const float4 wv = *reinterpret_cast<const float4*>(w + (size_t)c * 4);
    const float* ip = in + (size_t)(bt - t) * C + c;  // batch base
    float s = 0.f;
    if (t >= 3) s += ip[(size_t)(t - 3) * C] * wv.x;
    if (t >= 2) s += ip[(size_t)(t - 2) * C] * wv.y;
    if (t >= 1) s += ip[(size_t)(t - 1) * C] * wv.z;
    s += ip[(size_t)t * C] * wv.w;
    out[idx] = s * sigmoidf_(s);
}

// ----------------- per-row (128) L2 norm, optional extra scale -------------
__global__ void l2norm_kernel(float* __restrict__ x, float scale)
{
    size_t row = blockIdx.x;
    int d = threadIdx.x;  // 128 threads
    float v = x[row * 128 + d];
    float s = v * v;
#pragma unroll
    for (int off = 16; off > 0; off >>= 1) s += __shfl_xor_sync(0xffffffffu, s, off);
    __shared__ float ws[4];
    if ((d & 31) == 0) ws[d >> 5] = s;
    __syncthreads();
    float tot = ws[0] + ws[1] + ws[2] + ws[3];
    x[row * 128 + d] = v * rsqrtf(tot + 1e-6f) * scale;
}

// -------------------- decay0 = exp(-A * softplus(graw+dtb)) ----------------
__global__ void decay_kernel(const float* __restrict__ graw, const float* __restrict__ dt_bias,
                             const float* __restrict__ A_log, float* __restrict__ dec, long total)
{
    long idx = (long)blockIdx.x * blockDim.x + threadIdx.x;
    if (idx >= total) return;
    int ch = (int)(idx % 2048);
    int h = ch >> 7;
    float x = graw[idx] + dt_bias[ch];
    dec[idx] = expf(-expf(A_log[h]) * softplusf_(x));
}

__global__ void sigmoid_kernel(const float* __restrict__ in, float* __restrict__ out, long total)
{
    long idx = (long)blockIdx.x * blockDim.x + threadIdx.x;
    if (idx >= total) return;
    out[idx] = sigmoidf_(in[idx]);
}

// --------------------------- delta-rule microscan --------------------------
// grid (4, H, B); block 128. CTA owns columns v in [32*split, 32*split+32).
// warp w owns d-range [32w, 32w+32); lane c owns column (vbase + c).
__global__ void scan_kernel(const float* __restrict__ qp, const float* __restrict__ kp,
                            const float* __restrict__ vp, const float* __restrict__ dec,
                            const float* __restrict__ beta,
                            const float* __restrict__ dt_bias, const float* __restrict__ A_log,
                            const float* __restrict__ micro_logits,
                            float* __restrict__ o_mix, int T)
{
    const int split = blockIdx.x;
    const int h = blockIdx.y;
    const int b = blockIdx.z;
    const int tid = threadIdx.x;
    const int w = tid >> 5;
    const int c = tid & 31;
    const int vcol = split * 32 + c;

    __shared__ float sq[128], sk[512], sv[512], sdec[128], sdf[128], red[128];
    __shared__ float sb[4], swm[4];

    // decay_fill (per h,d): exp(-A * softplus(FILL + dt_bias))
    {
        float dtb = dt_bias[h * 128 + tid];
        float xx = -10000.0f + dtb;
        sdf[tid] = expf(-expf(A_log[h]) * softplusf_(xx));
    }
    if (tid == 0) {
        float m0 = micro_logits[h * 4 + 0], m1 = micro_logits[h * 4 + 1];
        float m2 = micro_logits[h * 4 + 2], m3 = micro_logits[h * 4 + 3];
        float mx = fmaxf(fmaxf(m0, m1), fmaxf(m2, m3));
        float e0 = expf(m0 - mx), e1 = expf(m1 - mx), e2 = expf(m2 - mx), e3 = expf(m3 - mx);
        float inv = 1.f / (e0 + e1 + e2 + e3);
        swm[0] = e0 * inv; swm[1] = e1 * inv; swm[2] = e2 * inv; swm[3] = e3 * inv;
    }

    float S[32];
#pragma unroll
    for (int i = 0; i < 32; i++) S[i] = 0.f;
    __syncthreads();

    for (int t = 0; t < T; t++) {
        const size_t base = ((size_t)(b * T + t) * H_ + h);
        const size_t qoff = base * 128;
        const size_t koff = base * 512;
        sq[tid]   = qp[qoff + tid];
        sdec[tid] = dec[qoff + tid];
#pragma unroll
        for (int j = 0; j < 4; j++) {
            sk[j * 128 + tid] = kp[koff + j * 128 + tid];
            sv[j * 128 + tid] = vp[koff + j * 128 + tid];
        }
        if (tid < 4) sb[tid] = beta[base * 4 + tid];
        __syncthreads();

        float oacc = 0.f;
#pragma unroll
        for (int j = 0; j < 4; j++) {
            const float* kj = &sk[j * 128 + w * 32];
            const float* dd = (j == 0) ? &sdec[w * 32] : &sdf[w * 32];
            float up = 0.f;
#pragma unroll
            for (int i = 0; i < 32; i++) {
                float s = S[i] * dd[i];
                S[i] = s;
                up = fmaf(kj[i], s, up);
            }
            red[tid] = up;
            __syncthreads();
            float u = red[c] + red[32 + c] + red[64 + c] + red[96 + c];
            __syncthreads();
            float coef = sb[j] * (sv[j * 128 + vcol] - u);
            float dj = 0.f;
#pragma unroll
            for (int i = 0; i < 32; i++) {
                float s = fmaf(coef, kj[i], S[i]);
                S[i] = s;
                dj = fmaf(sq[w * 32 + i], s, dj);
            }
            oacc = fmaf(swm[j], dj, oacc);
        }
        red[tid] = oacc;
        __syncthreads();
        if (w == 0) {
            o_mix[qoff + vcol] = red[c] + red[32 + c] + red[64 + c] + red[96 + c];
        }
        __syncthreads();
    }
}

// ------------ output norm: o * rsqrt(mean(o^2)+eps) * w * sigm(gate) -------
__global__ void post_kernel(const float* __restrict__ omix, const float* __restrict__ gate,
                            const float* __restrict__ onw, float* __restrict__ ofin)
{
    size_t row = blockIdx.x;
    int v = threadIdx.x;  // 128
    float o = omix[row * 128 + v];
    float s = o * o;
#pragma unroll
    for (int off = 16; off > 0; off >>= 1) s += __shfl_xor_sync(0xffffffffu, s, off);
    __shared__ float ws[4];
    if ((v & 31) == 0) ws[v >> 5] = s;
    __syncthreads();
    float mean = (ws[0] + ws[1] + ws[2] + ws[3]) * (1.f / 128.f);
    ofin[row * 128 + v] = o * rsqrtf(mean + 1e-5f) * onw[v] * sigmoidf_(gate[row * 128 + v]);
}

// ---------------------------------------------------------------------------
extern "C" void kernel_launch(void* const* d_in, const int* in_sizes, int n_in,
                              void* d_out, int out_size)
{
    const float* x       = (const float*)d_in[0];
    const float* q_proj  = (const float*)d_in[1];
    const float* k_proj  = (const float*)d_in[2];
    const float* v_proj  = (const float*)d_in[3];
    const float* q_convw = (const float*)d_in[4];
    const float* k_convw = (const float*)d_in[5];
    const float* v_convw = (const float*)d_in[6];
    const float* f1_w    = (const float*)d_in[7];
    const float* f2_w    = (const float*)d_in[8];
    const float* b_proj  = (const float*)d_in[9];
    const float* micro   = (const float*)d_in[10];
    const float* A_log   = (const float*)d_in[11];
    const float* dt_bias = (const float*)d_in[12];
    const float* g1_w    = (const float*)d_in[13];
    const float* g2_w    = (const float*)d_in[14];
    const float* g2_b    = (const float*)d_in[15];
    const float* o_normw = (const float*)d_in[16];
    const float* o_proj  = (const float*)d_in[17];
    float* out = (float*)d_out;

    const int T = T_;
    const int BT = in_sizes[0] / HID_;   // B * T
    const int B = BT / T;

    float *qpre, *kpre, *vpre, *bpre, *f1h, *g1h, *graw, *gate;
    float *qb, *kb, *vb, *decb, *betab, *omix, *ofin;
    cudaGetSymbolAddress((void**)&qpre,  g_qpre);
    cudaGetSymbolAddress((void**)&kpre,  g_kpre);
    cudaGetSymbolAddress((void**)&vpre,  g_vpre);
    cudaGetSymbolAddress((void**)&bpre,  g_bpre);
    cudaGetSymbolAddress((void**)&f1h,   g_f1h);
    cudaGetSymbolAddress((void**)&g1h,   g_g1h);
    cudaGetSymbolAddress((void**)&graw,  g_graw);
    cudaGetSymbolAddress((void**)&gate,  g_gate);
    cudaGetSymbolAddress((void**)&qb,    g_qb);
    cudaGetSymbolAddress((void**)&kb,    g_kb);
    cudaGetSymbolAddress((void**)&vb,    g_vb);
    cudaGetSymbolAddress((void**)&decb,  g_dec);
    cudaGetSymbolAddress((void**)&betab, g_beta);
    cudaGetSymbolAddress((void**)&omix,  g_omix);
    cudaGetSymbolAddress((void**)&ofin,  g_ofin);

    auto g2d = [](int N, int M) { return dim3((unsigned)((N + GBN - 1) / GBN),
                                              (unsigned)((M + GBM - 1) / GBM)); };

    // projections off x
    gemm_nt_kernel<<<g2d(KD_,  BT), 256>>>(x, q_proj, qpre, nullptr, BT, KD_,  HID_);
    gemm_nt_kernel<<<g2d(KDR_, BT), 256>>>(x, k_proj, kpre, nullptr, BT, KDR_, HID_);
    gemm_nt_kernel<<<g2d(VDR_, BT), 256>>>(x, v_proj, vpre, nullptr, BT, VDR_, HID_);
    gemm_nt_kernel<<<g2d(H_*R_, BT), 256>>>(x, b_proj, bpre, nullptr, BT, H_ * R_, HID_);
    gemm_nt_kernel<<<g2d(128, BT), 256>>>(x, f1_w, f1h, nullptr, BT, 128, HID_);
    gemm_nt_kernel<<<g2d(128, BT), 256>>>(x, g1_w, g1h, nullptr, BT, 128, HID_);
    // low-rank expansions
    gemm_nt_kernel<<<g2d(KD_, BT), 256>>>(f1h, f2_w, graw, nullptr, BT, KD_, 128);
    gemm_nt_kernel<<<g2d(KD_, BT), 256>>>(g1h, g2_w, gate, g2_b,    BT, KD_, 128);

    // conv + silu
    long nq = (long)BT * KD_;
    long nk = (long)BT * KDR_;
    conv_silu_kernel<<<(unsigned)((nq + 255) / 256), 256>>>(qpre, q_convw, qb, KD_,  nq, T);
    conv_silu_kernel<<<(unsigned)((nk + 255) / 256), 256>>>(kpre, k_convw, kb, KDR_, nk, T);
    conv_silu_kernel<<<(unsigned)((nk + 255) / 256), 256>>>(vpre, v_convw, vb, VDR_, nk, T);

    // norms + activations
    l2norm_kernel<<<(unsigned)(BT * H_), 128>>>(qb, 0.08838834764831843f);  // D^-0.5
    l2norm_kernel<<<(unsigned)(BT * H_ * R_), 128>>>(kb, 1.0f);
    decay_kernel<<<(unsigned)((nq + 255) / 256), 256>>>(graw, dt_bias, A_log, decb, nq);
    long nb = (long)BT * H_ * R_;
    sigmoid_kernel<<<(unsigned)((nb + 255) / 256), 256>>>(bpre, betab, nb);

    // sequential microscan (column-split over DV)
    dim3 sgrid(4, H_, (unsigned)B);
    scan_kernel<<<sgrid, 128>>>(qb, kb, vb, decb, betab, dt_bias, A_log, micro, omix, T);

    // output norm + gate, then o_proj
    post_kernel<<<(unsigned)(BT * H_), 128>>>(omix, gate, o_normw, ofin);
    gemm_nt_kernel<<<g2d(HID_, BT), 256>>>(ofin, o_proj, out, nullptr, BT, HID_, HID_);
}

// round 9
// speedup vs baseline: 2.0713x; 2.0713x over previous
#include <cuda_runtime.h>
#include <cuda_bf16.h>
#include <math.h>
#include <stdint.h>

// ---------------------------------------------------------------------------
// MicrostepKimiDeltaAttention — Round 7: GEMMs via mma.sync (split-bf16 3-pass)
// tcgen05 is rejected by this toolchain (PTX target sm_103 without 'a'), so
// the tensor path uses baseline ldmatrix + mma.sync.m16n8k16.bf16.
// B=2, T=1024, HID=2048, H=16, D=DV=128, R=4, CONV=4
// ---------------------------------------------------------------------------

#define H_    16
#define D_    128
#define DV_   128
#define R_    4
#define HID_  2048
#define T_    1024
#define B_MAX 2
#define KD_   (H_ * D_)        // 2048
#define KDR_  (KD_ * R_)       // 8192
#define VDR_  (H_ * DV_ * R_)  // 8192

// ------------------------- f32 scratch (device globals) --------------------
__device__ float g_qpre [B_MAX * T_ * KD_];
__device__ float g_kpre [B_MAX * T_ * KDR_];
__device__ float g_vpre [B_MAX * T_ * VDR_];
__device__ float g_bpre [B_MAX * T_ * H_ * R_];
__device__ float g_f1h  [B_MAX * T_ * 128];
__device__ float g_g1h  [B_MAX * T_ * 128];
__device__ float g_graw [B_MAX * T_ * KD_];
__device__ float g_gate [B_MAX * T_ * H_ * DV_];
__device__ float g_qb   [B_MAX * T_ * KD_];
__device__ float g_kb   [B_MAX * T_ * KDR_];
__device__ float g_vb   [B_MAX * T_ * VDR_];
__device__ float g_dec  [B_MAX * T_ * KD_];
__device__ float g_beta [B_MAX * T_ * H_ * R_];
__device__ float g_omix [B_MAX * T_ * H_ * DV_];
__device__ float g_ofin [B_MAX * T_ * H_ * DV_];

// ------------------------- bf16 hi/lo scratch ------------------------------
#define DECL_HL(name, n) \
    __device__ __align__(16) __nv_bfloat16 name##_hi[n]; \
    __device__ __align__(16) __nv_bfloat16 name##_lo[n];

DECL_HL(g_x,   B_MAX * T_ * HID_)
DECL_HL(g_wq,  KD_ * HID_)
DECL_HL(g_wk,  KDR_ * HID_)
DECL_HL(g_wv,  VDR_ * HID_)
DECL_HL(g_wb,  H_ * R_ * HID_)
DECL_HL(g_wf1, 128 * HID_)
DECL_HL(g_wg1, 128 * HID_)
DECL_HL(g_wf2, KD_ * 128)
DECL_HL(g_wg2, KD_ * 128)
DECL_HL(g_wo,  HID_ * (H_ * DV_))
DECL_HL(g_af1, B_MAX * T_ * 128)
DECL_HL(g_ag1, B_MAX * T_ * 128)
DECL_HL(g_aof, B_MAX * T_ * H_ * DV_)

static __device__ __forceinline__ float sigmoidf_(float x) { return 1.f / (1.f + expf(-x)); }
static __device__ __forceinline__ float softplusf_(float x) { return (x > 20.f) ? x : log1pf(expf(x)); }

// ------------------------------ split f32 -> bf16 hi/lo --------------------
__global__ void split_kernel(const float* __restrict__ in,
                             __nv_bfloat16* __restrict__ hi,
                             __nv_bfloat16* __restrict__ lo, long n)
{
    long i = (long)blockIdx.x * blockDim.x + threadIdx.x;
    if (i >= n) return;
    float x = in[i];
    __nv_bfloat16 h = __float2bfloat16(x);
    float r = x - __bfloat162float(h);
    hi[i] = h;
    lo[i] = __float2bfloat16(r);
}

// =================== mma.sync split-bf16 GEMM: C = A @ W^T ==================
// A: [M,K] (hi/lo bf16), W: [N,K] (hi/lo bf16), C: [M,N] f32 (+bias optional)
// M % 128 == 0, K % 64 == 0; N arbitrary (guarded).
#define TBM 128
#define TBN 128
#define TBK 64
#define SM_AHI 0
#define SM_ALO 16384
#define SM_WHI 32768
#define SM_WLO 49152
#define STAGE_BYTES 65536
#define NSTAGE 3
#define TG_SMEM (NSTAGE * STAGE_BYTES)

static __device__ __forceinline__ uint32_t s2u(const void* p) {
    uint32_t a;
    asm("{ .reg .u64 t; cvta.to.shared.u64 t, %1; cvt.u32.u64 %0, t; }" : "=r"(a) : "l"(p));
    return a;
}
// SW128 swizzle of (row, byte-col) inside a 128B-row tile
static __device__ __forceinline__ uint32_t swaddr(int row, int colb) {
    return (uint32_t)(row * 128 + (colb ^ ((row & 7) << 4)));
}
static __device__ __forceinline__ void cp16(uint32_t s, const void* g, uint32_t bytes) {
    asm volatile("cp.async.cg.shared.global [%0], [%1], 16, %2;" :: "r"(s), "l"(g), "r"(bytes));
}
static __device__ __forceinline__ void ldsm4(uint32_t* r, uint32_t addr) {
    asm volatile("ldmatrix.sync.aligned.m8n8.x4.shared.b16 {%0,%1,%2,%3}, [%4];"
                 : "=r"(r[0]), "=r"(r[1]), "=r"(r[2]), "=r"(r[3]) : "r"(addr));
}
static __device__ __forceinline__ void mma16816(float* d, const uint32_t* a, const uint32_t* b) {
    asm volatile(
        "mma.sync.aligned.m16n8k16.row.col.f32.bf16.bf16.f32 "
        "{%0,%1,%2,%3}, {%4,%5,%6,%7}, {%8,%9}, {%0,%1,%2,%3};"
        : "+f"(d[0]), "+f"(d[1]), "+f"(d[2]), "+f"(d[3])
        : "r"(a[0]), "r"(a[1]), "r"(a[2]), "r"(a[3]), "r"(b[0]), "r"(b[1]));
}

static __device__ __forceinline__ void fill_stage(
    uint32_t st,
    const __nv_bfloat16* __restrict__ Ahi, const __nv_bfloat16* __restrict__ Alo,
    const __nv_bfloat16* __restrict__ Whi, const __nv_bfloat16* __restrict__ Wlo,
    int bm, int bn, int k0, int N, int K, int tid)
{
    // A tile: 128 rows x 64 bf16 (128B/row) = 1024 x 16B per operand half
#pragma unroll
    for (int it = 0; it < 4; it++) {
        int q = tid + it * 256;
        int row = q >> 3, c16 = q & 7;
        uint32_t so = swaddr(row, c16 * 16);
        size_t go = (size_t)(bm + row) * K + k0 + c16 * 8;
        cp16(st + SM_AHI + so, Ahi + go, 16);
        cp16(st + SM_ALO + so, Alo + go, 16);
    }
    // W tile: 128 rows x 64 bf16 per operand half (N-guarded, zero-fill)
#pragma unroll
    for (int it = 0; it < 4; it++) {
        int q = tid + it * 256;
        int row = q >> 3, c16 = q & 7;
        uint32_t so = swaddr(row, c16 * 16);
        int n = bn + row;
        uint32_t vb = (n < N) ? 16u : 0u;
        size_t go = (size_t)((n < N) ? n : 0) * K + k0 + c16 * 8;
        cp16(st + SM_WHI + so, Whi + go, vb);
        cp16(st + SM_WLO + so, Wlo + go, vb);
    }
    asm volatile("cp.async.commit_group;" ::: "memory");
}

__global__ void __launch_bounds__(256, 1) tgemm_kernel(
    const __nv_bfloat16* __restrict__ Ahi, const __nv_bfloat16* __restrict__ Alo,
    const __nv_bfloat16* __restrict__ Whi, const __nv_bfloat16* __restrict__ Wlo,
    float* __restrict__ C, const float* __restrict__ bias, int M, int N, int K)
{
    extern __shared__ char smem[];
    const uint32_t sb = s2u(smem);
    const int tid = threadIdx.x;
    const int wid = tid >> 5;
    const int lane = tid & 31;
    const int wm = wid & 3;          // warp row  (32 rows each)
    const int wn = wid >> 2;         // warp col  (64 cols each)
    const int bn = blockIdx.x * TBN;
    const int bm = blockIdx.y * TBM;
    const int chunks = K / TBK;

    float acc[2][8][4];
#pragma unroll
    for (int mi = 0; mi < 2; mi++)
#pragma unroll
        for (int ni = 0; ni < 8; ni++)
#pragma unroll
            for (int r = 0; r < 4; r++) acc[mi][ni][r] = 0.f;

    // prologue
    fill_stage(sb, Ahi, Alo, Whi, Wlo, bm, bn, 0, N, K, tid);
    if (chunks > 1)
        fill_stage(sb + STAGE_BYTES, Ahi, Alo, Whi, Wlo, bm, bn, TBK, N, K, tid);

    // per-lane ldmatrix address components
    const int a_row = wm * 32 + (lane & 15);            // + mi*16
    const int a_cg  = (lane >> 4) * 16;                 // byte offset of k-group
    const int b_grp = lane >> 3;
    const int b_row = wn * 64 + ((b_grp >> 1) << 3) + (lane & 7);   // + p*16
    const int b_cg  = (b_grp & 1) * 16;                 // byte offset of k-group

    for (int c = 0; c < chunks; c++) {
        if (c + 1 < chunks) asm volatile("cp.async.wait_group 1;" ::: "memory");
        else                asm volatile("cp.async.wait_group 0;" ::: "memory");
        __syncthreads();

        if (c + 2 < chunks)
            fill_stage(sb + (uint32_t)((c + 2) % NSTAGE) * STAGE_BYTES,
                       Ahi, Alo, Whi, Wlo, bm, bn, (c + 2) * TBK, N, K, tid);

        const uint32_t st = sb + (uint32_t)(c % NSTAGE) * STAGE_BYTES;
#pragma unroll
        for (int k16 = 0; k16 < 4; k16++) {
            const int kb = k16 * 32;       // byte offset of this k16 in the row
            uint32_t ah[2][4], al[2][4], bh[8][2], bl[8][2];
#pragma unroll
            for (int mi = 0; mi < 2; mi++) {
                uint32_t so = swaddr(a_row + mi * 16, kb + a_cg);
                ldsm4(ah[mi], st + SM_AHI + so);
                ldsm4(al[mi], st + SM_ALO + so);
            }
#pragma unroll
            for (int p = 0; p < 4; p++) {
                uint32_t so = swaddr(b_row + p * 16, kb + b_cg);
                uint32_t th[4], tl[4];
                ldsm4(th, st + SM_WHI + so);
                ldsm4(tl, st + SM_WLO + so);
                bh[p * 2][0] = th[0]; bh[p * 2][1] = th[1];
                bh[p * 2 + 1][0] = th[2]; bh[p * 2 + 1][1] = th[3];
                bl[p * 2][0] = tl[0]; bl[p * 2][1] = tl[1];
                bl[p * 2 + 1][0] = tl[2]; bl[p * 2 + 1][1] = tl[3];
            }
#pragma unroll
            for (int mi = 0; mi < 2; mi++)
#pragma unroll
                for (int ni = 0; ni < 8; ni++) {
                    mma16816(acc[mi][ni], ah[mi], bh[ni]);
                    mma16816(acc[mi][ni], ah[mi], bl[ni]);
                    mma16816(acc[mi][ni], al[mi], bh[ni]);
                }
        }
        __syncthreads();
    }

    // ---- epilogue: direct stores (thread owns (row, col-pair) per mma tile)
    const int erow = bm + wm * 32 + (lane >> 2);
    const int ecol0 = bn + wn * 64 + (lane & 3) * 2;
#pragma unroll
    for (int mi = 0; mi < 2; mi++) {
#pragma unroll
        for (int ni = 0; ni < 8; ni++) {
            int col = ecol0 + ni * 8;
            if (col < N) {
                float b0 = bias ? bias[col] : 0.f;
                float b1 = bias ? bias[col + 1] : 0.f;
                float2 v0 = make_float2(acc[mi][ni][0] + b0, acc[mi][ni][1] + b1);
                float2 v1 = make_float2(acc[mi][ni][2] + b0, acc[mi][ni][3] + b1);
                *reinterpret_cast<float2*>(C + (size_t)(erow + mi * 16) * N + col) = v0;
                *reinterpret_cast<float2*>(C + (size_t)(erow + mi * 16 + 8) * N + col) = v1;
            }
        }
    }
}

// ------------------------- causal short conv + SiLU ------------------------
__global__ void conv_silu_kernel(const float* __restrict__ in, const float* __restrict__ w,
                                 float* __restrict__ out, int C, long total, int T)
{
    long idx = (long)blockIdx.x * blockDim.x + threadIdx.x;
    if (idx >= total) return;
    int c = (int)(idx % C);
    long bt = idx / C;
    int t = (int)(bt % T);
    const float4 wv = *reinterpret_cast<const float4*>(w + (size_t)c * 4);
    const float* ip = in + (size_t)(bt - t) * C + c;  // batch base
    float s = 0.f;
    if (t >= 3) s += ip[(size_t)(t - 3) * C] * wv.x;
    if (t >= 2) s += ip[(size_t)(t - 2) * C] * wv.y;
    if (t >= 1) s += ip[(size_t)(t - 1) * C] * wv.z;
    s += ip[(size_t)t * C] * wv.w;
    out[idx] = s * sigmoidf_(s);
}

// ----------------- per-row (128) L2 norm, optional extra scale -------------
__global__ void l2norm_kernel(float* __restrict__ x, float scale)
{
    size_t row = blockIdx.x;
    int d = threadIdx.x;  // 128 threads
    float v = x[row * 128 + d];
    float s = v * v;
#pragma unroll
    for (int off = 16; off > 0; off >>= 1) s += __shfl_xor_sync(0xffffffffu, s, off);
    __shared__ float ws[4];
    if ((d & 31) == 0) ws[d >> 5] = s;
    __syncthreads();
    float tot = ws[0] + ws[1] + ws[2] + ws[3];
    x[row * 128 + d] = v * rsqrtf(tot + 1e-6f) * scale;
}

// -------------------- decay0 = exp(-A * softplus(graw+dtb)) ----------------
__global__ void decay_kernel(const float* __restrict__ graw, const float* __restrict__ dt_bias,
                             const float* __restrict__ A_log, float* __restrict__ dec, long total)
{
    long idx = (long)blockIdx.x * blockDim.x + threadIdx.x;
    if (idx >= total) return;
    int ch = (int)(idx % 2048);
    int h = ch >> 7;
    float x = graw[idx] + dt_bias[ch];
    dec[idx] = expf(-expf(A_log[h]) * softplusf_(x));
}

__global__ void sigmoid_kernel(const float* __restrict__ in, float* __restrict__ out, long total)
{
    long idx = (long)blockIdx.x * blockDim.x + threadIdx.x;
    if (idx >= total) return;
    out[idx] = sigmoidf_(in[idx]);
}

// --------------------------- delta-rule microscan --------------------------
__global__ void scan_kernel(const float* __restrict__ qp, const float* __restrict__ kp,
                            const float* __restrict__ vp, const float* __restrict__ dec,
                            const float* __restrict__ beta,
                            const float* __restrict__ dt_bias, const float* __restrict__ A_log,
                            const float* __restrict__ micro_logits,
                            float* __restrict__ o_mix, int T)
{
    const int split = blockIdx.x;
    const int h = blockIdx.y;
    const int b = blockIdx.z;
    const int tid = threadIdx.x;
    const int w = tid >> 5;
    const int c = tid & 31;
    const int vcol = split * 32 + c;

    __shared__ float sq[128], sk[512], sv[512], sdec[128], sdf[128], red[128];
    __shared__ float sb[4], swm[4];

    {
        float dtb = dt_bias[h * 128 + tid];
        float xx = -10000.0f + dtb;
        sdf[tid] = expf(-expf(A_log[h]) * softplusf_(xx));
    }
    if (tid == 0) {
        float m0 = micro_logits[h * 4 + 0], m1 = micro_logits[h * 4 + 1];
        float m2 = micro_logits[h * 4 + 2], m3 = micro_logits[h * 4 + 3];
        float mx = fmaxf(fmaxf(m0, m1), fmaxf(m2, m3));
        float e0 = expf(m0 - mx), e1 = expf(m1 - mx), e2 = expf(m2 - mx), e3 = expf(m3 - mx);
        float inv = 1.f / (e0 + e1 + e2 + e3);
        swm[0] = e0 * inv; swm[1] = e1 * inv; swm[2] = e2 * inv; swm[3] = e3 * inv;
    }

    float S[32];
#pragma unroll
    for (int i = 0; i < 32; i++) S[i] = 0.f;
    __syncthreads();

    for (int t = 0; t < T; t++) {
        const size_t base = ((size_t)(b * T + t) * H_ + h);
        const size_t qoff = base * 128;
        const size_t koff = base * 512;
        sq[tid]   = qp[qoff + tid];
        sdec[tid] = dec[qoff + tid];
#pragma unroll
        for (int j = 0; j < 4; j++) {
            sk[j * 128 + tid] = kp[koff + j * 128 + tid];
            sv[j * 128 + tid] = vp[koff + j * 128 + tid];
        }
        if (tid < 4) sb[tid] = beta[base * 4 + tid];
        __syncthreads();

        float oacc = 0.f;
#pragma unroll
        for (int j = 0; j < 4; j++) {
            const float* kj = &sk[j * 128 + w * 32];
            const float* dd = (j == 0) ? &sdec[w * 32] : &sdf[w * 32];
            float up = 0.f;
#pragma unroll
            for (int i = 0; i < 32; i++) {
                float s = S[i] * dd[i];
                S[i] = s;
                up = fmaf(kj[i], s, up);
            }
            red[tid] = up;
            __syncthreads();
            float u = red[c] + red[32 + c] + red[64 + c] + red[96 + c];
            __syncthreads();
            float coef = sb[j] * (sv[j * 128 + vcol] - u);
            float dj = 0.f;
#pragma unroll
            for (int i = 0; i < 32; i++) {
                float s = fmaf(coef, kj[i], S[i]);
                S[i] = s;
                dj = fmaf(sq[w * 32 + i], s, dj);
            }
            oacc = fmaf(swm[j], dj, oacc);
        }
        red[tid] = oacc;
        __syncthreads();
        if (w == 0) {
            o_mix[qoff + vcol] = red[c] + red[32 + c] + red[64 + c] + red[96 + c];
        }
        __syncthreads();
    }
}

// ------------ output norm: o * rsqrt(mean(o^2)+eps) * w * sigm(gate) -------
__global__ void post_kernel(const float* __restrict__ omix, const float* __restrict__ gate,
                            const float* __restrict__ onw, float* __restrict__ ofin)
{
    size_t row = blockIdx.x;
    int v = threadIdx.x;  // 128
    float o = omix[row * 128 + v];
    float s = o * o;
#pragma unroll
    for (int off = 16; off > 0; off >>= 1) s += __shfl_xor_sync(0xffffffffu, s, off);
    __shared__ float ws[4];
    if ((v & 31) == 0) ws[v >> 5] = s;
    __syncthreads();
    float mean = (ws[0] + ws[1] + ws[2] + ws[3]) * (1.f / 128.f);
    ofin[row * 128 + v] = o * rsqrtf(mean + 1e-5f) * onw[v] * sigmoidf_(gate[row * 128 + v]);
}

// ---------------------------------------------------------------------------
extern "C" void kernel_launch(void* const* d_in, const int* in_sizes, int n_in,
                              void* d_out, int out_size)
{
    const float* x       = (const float*)d_in[0];
    const float* q_proj  = (const float*)d_in[1];
    const float* k_proj  = (const float*)d_in[2];
    const float* v_proj  = (const float*)d_in[3];
    const float* q_convw = (const float*)d_in[4];
    const float* k_convw = (const float*)d_in[5];
    const float* v_convw = (const float*)d_in[6];
    const float* f1_w    = (const float*)d_in[7];
    const float* f2_w    = (const float*)d_in[8];
    const float* b_proj  = (const float*)d_in[9];
    const float* micro   = (const float*)d_in[10];
    const float* A_log   = (const float*)d_in[11];
    const float* dt_bias = (const float*)d_in[12];
    const float* g1_w    = (const float*)d_in[13];
    const float* g2_w    = (const float*)d_in[14];
    const float* g2_b    = (const float*)d_in[15];
    const float* o_normw = (const float*)d_in[16];
    const float* o_proj  = (const float*)d_in[17];
    float* out = (float*)d_out;

    const int T = T_;
    const int BT = in_sizes[0] / HID_;   // B * T
    const int B = BT / T;

    cudaFuncSetAttribute(tgemm_kernel, cudaFuncAttributeMaxDynamicSharedMemorySize, TG_SMEM);

    float *qpre, *kpre, *vpre, *bpre, *f1h, *g1h, *graw, *gate;
    float *qb, *kb, *vb, *decb, *betab, *omix, *ofin;
    cudaGetSymbolAddress((void**)&qpre,  g_qpre);
    cudaGetSymbolAddress((void**)&kpre,  g_kpre);
    cudaGetSymbolAddress((void**)&vpre,  g_vpre);
    cudaGetSymbolAddress((void**)&bpre,  g_bpre);
    cudaGetSymbolAddress((void**)&f1h,   g_f1h);
    cudaGetSymbolAddress((void**)&g1h,   g_g1h);
    cudaGetSymbolAddress((void**)&graw,  g_graw);
    cudaGetSymbolAddress((void**)&gate,  g_gate);
    cudaGetSymbolAddress((void**)&qb,    g_qb);
    cudaGetSymbolAddress((void**)&kb,    g_kb);
    cudaGetSymbolAddress((void**)&vb,    g_vb);
    cudaGetSymbolAddress((void**)&decb,  g_dec);
    cudaGetSymbolAddress((void**)&betab, g_beta);
    cudaGetSymbolAddress((void**)&omix,  g_omix);
    cudaGetSymbolAddress((void**)&ofin,  g_ofin);

    __nv_bfloat16 *xhi, *xlo, *qwh, *qwl, *kwh, *kwl, *vwh, *vwl, *bwh, *bwl;
    __nv_bfloat16 *f1wh, *f1wl, *g1wh, *g1wl, *f2wh, *f2wl, *g2wh, *g2wl, *owh, *owl;
    __nv_bfloat16 *af1h, *af1l, *ag1h, *ag1l, *aofh, *aofl;
    cudaGetSymbolAddress((void**)&xhi,  g_x_hi);   cudaGetSymbolAddress((void**)&xlo,  g_x_lo);
    cudaGetSymbolAddress((void**)&qwh,  g_wq_hi);  cudaGetSymbolAddress((void**)&qwl,  g_wq_lo);
    cudaGetSymbolAddress((void**)&kwh,  g_wk_hi);  cudaGetSymbolAddress((void**)&kwl,  g_wk_lo);
    cudaGetSymbolAddress((void**)&vwh,  g_wv_hi);  cudaGetSymbolAddress((void**)&vwl,  g_wv_lo);
    cudaGetSymbolAddress((void**)&bwh,  g_wb_hi);  cudaGetSymbolAddress((void**)&bwl,  g_wb_lo);
    cudaGetSymbolAddress((void**)&f1wh, g_wf1_hi); cudaGetSymbolAddress((void**)&f1wl, g_wf1_lo);
    cudaGetSymbolAddress((void**)&g1wh, g_wg1_hi); cudaGetSymbolAddress((void**)&g1wl, g_wg1_lo);
    cudaGetSymbolAddress((void**)&f2wh, g_wf2_hi); cudaGetSymbolAddress((void**)&f2wl, g_wf2_lo);
    cudaGetSymbolAddress((void**)&g2wh, g_wg2_hi); cudaGetSymbolAddress((void**)&g2wl, g_wg2_lo);
    cudaGetSymbolAddress((void**)&owh,  g_wo_hi);  cudaGetSymbolAddress((void**)&owl,  g_wo_lo);
    cudaGetSymbolAddress((void**)&af1h, g_af1_hi); cudaGetSymbolAddress((void**)&af1l, g_af1_lo);
    cudaGetSymbolAddress((void**)&ag1h, g_ag1_hi); cudaGetSymbolAddress((void**)&ag1l, g_ag1_lo);
    cudaGetSymbolAddress((void**)&aofh, g_aof_hi); cudaGetSymbolAddress((void**)&aofl, g_aof_lo);

    auto splg = [](long n) { return (unsigned)((n + 255) / 256); };

    // split inputs/weights into bf16 hi/lo
    long nx = (long)BT * HID_;
    split_kernel<<<splg(nx), 256>>>(x, xhi, xlo, nx);
    split_kernel<<<splg((long)KD_ * HID_),  256>>>(q_proj, qwh, qwl, (long)KD_ * HID_);
    split_kernel<<<splg((long)KDR_ * HID_), 256>>>(k_proj, kwh, kwl, (long)KDR_ * HID_);
    split_kernel<<<splg((long)VDR_ * HID_), 256>>>(v_proj, vwh, vwl, (long)VDR_ * HID_);
    split_kernel<<<splg((long)H_ * R_ * HID_), 256>>>(b_proj, bwh, bwl, (long)H_ * R_ * HID_);
    split_kernel<<<splg((long)128 * HID_),  256>>>(f1_w, f1wh, f1wl, (long)128 * HID_);
    split_kernel<<<splg((long)128 * HID_),  256>>>(g1_w, g1wh, g1wl, (long)128 * HID_);
    split_kernel<<<splg((long)KD_ * 128),   256>>>(f2_w, f2wh, f2wl, (long)KD_ * 128);
    split_kernel<<<splg((long)KD_ * 128),   256>>>(g2_w, g2wh, g2wl, (long)KD_ * 128);
    split_kernel<<<splg((long)HID_ * KD_),  256>>>(o_proj, owh, owl, (long)HID_ * KD_);

    auto tg = [&](const __nv_bfloat16* ah, const __nv_bfloat16* al,
                  const __nv_bfloat16* wh, const __nv_bfloat16* wl,
                  float* C, const float* bias, int M, int N, int K) {
        dim3 grid((unsigned)((N + TBN - 1) / TBN), (unsigned)(M / TBM));
        tgemm_kernel<<<grid, 256, TG_SMEM>>>(ah, al, wh, wl, C, bias, M, N, K);
    };

    // projections off x
    tg(xhi, xlo, qwh, qwl, qpre, nullptr, BT, KD_,  HID_);
    tg(xhi, xlo, kwh, kwl, kpre, nullptr, BT, KDR_, HID_);
    tg(xhi, xlo, vwh, vwl, vpre, nullptr, BT, VDR_, HID_);
    tg(xhi, xlo, bwh, bwl, bpre, nullptr, BT, H_ * R_, HID_);
    tg(xhi, xlo, f1wh, f1wl, f1h, nullptr, BT, 128, HID_);
    tg(xhi, xlo, g1wh, g1wl, g1h, nullptr, BT, 128, HID_);
    // low-rank expansions (K=128)
    long nh = (long)BT * 128;
    split_kernel<<<splg(nh), 256>>>(f1h, af1h, af1l, nh);
    split_kernel<<<splg(nh), 256>>>(g1h, ag1h, ag1l, nh);
    tg(af1h, af1l, f2wh, f2wl, graw, nullptr, BT, KD_, 128);
    tg(ag1h, ag1l, g2wh, g2wl, gate, g2_b,    BT, KD_, 128);

    // conv + silu
    long nq = (long)BT * KD_;
    long nk = (long)BT * KDR_;
    conv_silu_kernel<<<splg(nq), 256>>>(qpre, q_convw, qb, KD_,  nq, T);
    conv_silu_kernel<<<splg(nk), 256>>>(kpre, k_convw, kb, KDR_, nk, T);
    conv_silu_kernel<<<splg(nk), 256>>>(vpre, v_convw, vb, VDR_, nk, T);

    // norms + activations
    l2norm_kernel<<<(unsigned)(BT * H_), 128>>>(qb, 0.08838834764831843f);  // D^-0.5
    l2norm_kernel<<<(unsigned)(BT * H_ * R_), 128>>>(kb, 1.0f);
    decay_kernel<<<splg(nq), 256>>>(graw, dt_bias, A_log, decb, nq);
    long nb = (long)BT * H_ * R_;
    sigmoid_kernel<<<splg(nb), 256>>>(bpre, betab, nb);

    // sequential microscan (column-split over DV)
    dim3 sgrid(4, H_, (unsigned)B);
    scan_kernel<<<sgrid, 128>>>(qb, kb, vb, decb, betab, dt_bias, A_log, micro, omix, T);

    // output norm + gate, then o_proj (split-bf16 tensor GEMM)
    post_kernel<<<(unsigned)(BT * H_), 128>>>(omix, gate, o_normw, ofin);
    long no = (long)BT * KD_;
    split_kernel<<<splg(no), 256>>>(ofin, aofh, aofl, no);
    tg(aofh, aofl, owh, owl, out, nullptr, BT, HID_, KD_);
}

// round 10
// speedup vs baseline: 2.0772x; 1.0028x over previous
#include <cuda_runtime.h>
#include <cuda_bf16.h>
#include <math.h>
#include <stdint.h>

// ---------------------------------------------------------------------------
// MicrostepKimiDeltaAttention — Round 7: GEMMs via mma.sync (split-bf16 3-pass)
// tcgen05 is rejected by this toolchain (PTX target sm_103 without 'a'), so
// the tensor path uses baseline ldmatrix + mma.sync.m16n8k16.bf16.
// B=2, T=1024, HID=2048, H=16, D=DV=128, R=4, CONV=4
// ---------------------------------------------------------------------------

#define H_    16
#define D_    128
#define DV_   128
#define R_    4
#define HID_  2048
#define T_    1024
#define B_MAX 2
#define KD_   (H_ * D_)        // 2048
#define KDR_  (KD_ * R_)       // 8192
#define VDR_  (H_ * DV_ * R_)  // 8192

// ------------------------- f32 scratch (device globals) --------------------
__device__ float g_qpre [B_MAX * T_ * KD_];
__device__ float g_kpre [B_MAX * T_ * KDR_];
__device__ float g_vpre [B_MAX * T_ * VDR_];
__device__ float g_bpre [B_MAX * T_ * H_ * R_];
__device__ float g_f1h  [B_MAX * T_ * 128];
__device__ float g_g1h  [B_MAX * T_ * 128];
__device__ float g_graw [B_MAX * T_ * KD_];
__device__ float g_gate [B_MAX * T_ * H_ * DV_];
__device__ float g_qb   [B_MAX * T_ * KD_];
__device__ float g_kb   [B_MAX * T_ * KDR_];
__device__ float g_vb   [B_MAX * T_ * VDR_];
__device__ float g_dec  [B_MAX * T_ * KD_];
__device__ float g_beta [B_MAX * T_ * H_ * R_];
__device__ float g_omix [B_MAX * T_ * H_ * DV_];
__device__ float g_ofin [B_MAX * T_ * H_ * DV_];

// ------------------------- bf16 hi/lo scratch ------------------------------
#define DECL_HL(name, n) \
    __device__ __align__(16) __nv_bfloat16 name##_hi[n]; \
    __device__ __align__(16) __nv_bfloat16 name##_lo[n];

DECL_HL(g_x,   B_MAX * T_ * HID_)
DECL_HL(g_wq,  KD_ * HID_)
DECL_HL(g_wk,  KDR_ * HID_)
DECL_HL(g_wv,  VDR_ * HID_)
DECL_HL(g_wb,  H_ * R_ * HID_)
DECL_HL(g_wf1, 128 * HID_)
DECL_HL(g_wg1, 128 * HID_)
DECL_HL(g_wf2, KD_ * 128)
DECL_HL(g_wg2, KD_ * 128)
DECL_HL(g_wo,  HID_ * (H_ * DV_))
DECL_HL(g_af1, B_MAX * T_ * 128)
DECL_HL(g_ag1, B_MAX * T_ * 128)
DECL_HL(g_aof, B_MAX * T_ * H_ * DV_)

static __device__ __forceinline__ float sigmoidf_(float x) { return 1.f / (1.f + expf(-x)); }
static __device__ __forceinline__ float softplusf_(float x) { return (x > 20.f) ? x : log1pf(expf(x)); }

// ------------------------------ split f32 -> bf16 hi/lo --------------------
__global__ void split_kernel(const float* __restrict__ in,
                             __nv_bfloat16* __restrict__ hi,
                             __nv_bfloat16* __restrict__ lo, long n)
{
    long i = (long)blockIdx.x * blockDim.x + threadIdx.x;
    if (i >= n) return;
    float x = in[i];
    __nv_bfloat16 h = __float2bfloat16(x);
    float r = x - __bfloat162float(h);
    hi[i] = h;
    lo[i] = __float2bfloat16(r);
}

// =================== mma.sync split-bf16 GEMM: C = A @ W^T ==================
// A: [M,K] (hi/lo bf16), W: [N,K] (hi/lo bf16), C: [M,N] f32 (+bias optional)
// M % 128 == 0, K % 64 == 0; N arbitrary (guarded).
#define TBM 128
#define TBN 128
#define TBK 64
#define SM_AHI 0
#define SM_ALO 16384
#define SM_WHI 32768
#define SM_WLO 49152
#define STAGE_BYTES 65536
#define NSTAGE 3
#define TG_SMEM (NSTAGE * STAGE_BYTES)

static __device__ __forceinline__ uint32_t s2u(const void* p) {
    uint32_t a;
    asm("{ .reg .u64 t; cvta.to.shared.u64 t, %1; cvt.u32.u64 %0, t; }" : "=r"(a) : "l"(p));
    return a;
}
// SW128 swizzle of (row, byte-col) inside a 128B-row tile
static __device__ __forceinline__ uint32_t swaddr(int row, int colb) {
    return (uint32_t)(row * 128 + (colb ^ ((row & 7) << 4)));
}
static __device__ __forceinline__ void cp16(uint32_t s, const void* g, uint32_t bytes) {
    asm volatile("cp.async.cg.shared.global [%0], [%1], 16, %2;" :: "r"(s), "l"(g), "r"(bytes));
}
static __device__ __forceinline__ void ldsm4(uint32_t* r, uint32_t addr) {
    asm volatile("ldmatrix.sync.aligned.m8n8.x4.shared.b16 {%0,%1,%2,%3}, [%4];"
                 : "=r"(r[0]), "=r"(r[1]), "=r"(r[2]), "=r"(r[3]) : "r"(addr));
}
static __device__ __forceinline__ void mma16816(float* d, const uint32_t* a, const uint32_t* b) {
    asm volatile(
        "mma.sync.aligned.m16n8k16.row.col.f32.bf16.bf16.f32 "
        "{%0,%1,%2,%3}, {%4,%5,%6,%7}, {%8,%9}, {%0,%1,%2,%3};"
        : "+f"(d[0]), "+f"(d[1]), "+f"(d[2]), "+f"(d[3])
        : "r"(a[0]), "r"(a[1]), "r"(a[2]), "r"(a[3]), "r"(b[0]), "r"(b[1]));
}

static __device__ __forceinline__ void fill_stage(
    uint32_t st,
    const __nv_bfloat16* __restrict__ Ahi, const __nv_bfloat16* __restrict__ Alo,
    const __nv_bfloat16* __restrict__ Whi, const __nv_bfloat16* __restrict__ Wlo,
    int bm, int bn, int k0, int N, int K, int tid)
{
    // A tile: 128 rows x 64 bf16 (128B/row) = 1024 x 16B per operand half
#pragma unroll
    for (int it = 0; it < 4; it++) {
        int q = tid + it * 256;
        int row = q >> 3, c16 = q & 7;
        uint32_t so = swaddr(row, c16 * 16);
        size_t go = (size_t)(bm + row) * K + k0 + c16 * 8;
        cp16(st + SM_AHI + so, Ahi + go, 16);
        cp16(st + SM_ALO + so, Alo + go, 16);
    }
    // W tile: 128 rows x 64 bf16 per operand half (N-guarded, zero-fill)
#pragma unroll
    for (int it = 0; it < 4; it++) {
        int q = tid + it * 256;
        int row = q >> 3, c16 = q & 7;
        uint32_t so = swaddr(row, c16 * 16);
        int n = bn + row;
        uint32_t vb = (n < N) ? 16u : 0u;
        size_t go = (size_t)((n < N) ? n : 0) * K + k0 + c16 * 8;
        cp16(st + SM_WHI + so, Whi + go, vb);
        cp16(st + SM_WLO + so, Wlo + go, vb);
    }
    asm volatile("cp.async.commit_group;" ::: "memory");
}

__global__ void __launch_bounds__(256, 1) tgemm_kernel(
    const __nv_bfloat16* __restrict__ Ahi, const __nv_bfloat16* __restrict__ Alo,
    const __nv_bfloat16* __restrict__ Whi, const __nv_bfloat16* __restrict__ Wlo,
    float* __restrict__ C, const float* __restrict__ bias, int M, int N, int K)
{
    extern __shared__ char smem[];
    const uint32_t sb = s2u(smem);
    const int tid = threadIdx.x;
    const int wid = tid >> 5;
    const int lane = tid & 31;
    const int wm = wid & 3;          // warp row  (32 rows each)
    const int wn = wid >> 2;         // warp col  (64 cols each)
    const int bn = blockIdx.x * TBN;
    const int bm = blockIdx.y * TBM;
    const int chunks = K / TBK;

    float acc[2][8][4];
#pragma unroll
    for (int mi = 0; mi < 2; mi++)
#pragma unroll
        for (int ni = 0; ni < 8; ni++)
#pragma unroll
            for (int r = 0; r < 4; r++) acc[mi][ni][r] = 0.f;

    // prologue
    fill_stage(sb, Ahi, Alo, Whi, Wlo, bm, bn, 0, N, K, tid);
    if (chunks > 1)
        fill_stage(sb + STAGE_BYTES, Ahi, Alo, Whi, Wlo, bm, bn, TBK, N, K, tid);

    // per-lane ldmatrix address components
    const int a_row = wm * 32 + (lane & 15);            // + mi*16
    const int a_cg  = (lane >> 4) * 16;                 // byte offset of k-group
    const int b_grp = lane >> 3;
    const int b_row = wn * 64 + ((b_grp >> 1) << 3) + (lane & 7);   // + p*16
    const int b_cg  = (b_grp & 1) * 16;                 // byte offset of k-group

    for (int c = 0; c < chunks; c++) {
        if (c + 1 < chunks) asm volatile("cp.async.wait_group 1;" ::: "memory");
        else                asm volatile("cp.async.wait_group 0;" ::: "memory");
        __syncthreads();

        if (c + 2 < chunks)
            fill_stage(sb + (uint32_t)((c + 2) % NSTAGE) * STAGE_BYTES,
                       Ahi, Alo, Whi, Wlo, bm, bn, (c + 2) * TBK, N, K, tid);

        const uint32_t st = sb + (uint32_t)(c % NSTAGE) * STAGE_BYTES;
#pragma unroll
        for (int k16 = 0; k16 < 4; k16++) {
            const int kb = k16 * 32;       // byte offset of this k16 in the row
            uint32_t ah[2][4], al[2][4], bh[8][2], bl[8][2];
#pragma unroll
            for (int mi = 0; mi < 2; mi++) {
                uint32_t so = swaddr(a_row + mi * 16, kb + a_cg);
                ldsm4(ah[mi], st + SM_AHI + so);
                ldsm4(al[mi], st + SM_ALO + so);
            }
#pragma unroll
            for (int p = 0; p < 4; p++) {
                uint32_t so = swaddr(b_row + p * 16, kb + b_cg);
                uint32_t th[4], tl[4];
                ldsm4(th, st + SM_WHI + so);
                ldsm4(tl, st + SM_WLO + so);
                bh[p * 2][0] = th[0]; bh[p * 2][1] = th[1];
                bh[p * 2 + 1][0] = th[2]; bh[p * 2 + 1][1] = th[3];
                bl[p * 2][0] = tl[0]; bl[p * 2][1] = tl[1];
                bl[p * 2 + 1][0] = tl[2]; bl[p * 2 + 1][1] = tl[3];
            }
#pragma unroll
            for (int mi = 0; mi < 2; mi++)
#pragma unroll
                for (int ni = 0; ni < 8; ni++) {
                    mma16816(acc[mi][ni], ah[mi], bh[ni]);
                    mma16816(acc[mi][ni], ah[mi], bl[ni]);
                    mma16816(acc[mi][ni], al[mi], bh[ni]);
                }
        }
        __syncthreads();
    }

    // ---- epilogue: direct stores (thread owns (row, col-pair) per mma tile)
    const int erow = bm + wm * 32 + (lane >> 2);
    const int ecol0 = bn + wn * 64 + (lane & 3) * 2;
#pragma unroll
    for (int mi = 0; mi < 2; mi++) {
#pragma unroll
        for (int ni = 0; ni < 8; ni++) {
            int col = ecol0 + ni * 8;
            if (col < N) {
                float b0 = bias ? bias[col] : 0.f;
                float b1 = bias ? bias[col + 1] : 0.f;
                float2 v0 = make_float2(acc[mi][ni][0] + b0, acc[mi][ni][1] + b1);
                float2 v1 = make_float2(acc[mi][ni][2] + b0, acc[mi][ni][3] + b1);
                *reinterpret_cast<float2*>(C + (size_t)(erow + mi * 16) * N + col) = v0;
                *reinterpret_cast<float2*>(C + (size_t)(erow + mi * 16 + 8) * N + col) = v1;
            }
        }
    }
}

// ------------------------- causal short conv + SiLU ------------------------
__global__ void conv_silu_kernel(const float* __restrict__ in, const float* __restrict__ w,
                                 float* __restrict__ out, int C, long total, int T)
{
    long idx = (long)blockIdx.x * blockDim.x + threadIdx.x;
    if (idx >= total) return;
    int c = (int)(idx % C);
    long bt = idx / C;
    int t = (int)(bt % T);
    const float4 wv = *reinterpret_cast<const float4*>(w + (size_t)c * 4);
    const float* ip = in + (size_t)(bt - t) * C + c;  // batch base
    float s = 0.f;
    if (t >= 3) s += ip[(size_t)(t - 3) * C] * wv.x;
    if (t >= 2) s += ip[(size_t)(t - 2) * C] * wv.y;
    if (t >= 1) s += ip[(size_t)(t - 1) * C] * wv.z;
    s += ip[(size_t)t * C] * wv.w;
    out[idx] = s * sigmoidf_(s);
}

// ----------------- per-row (128) L2 norm, optional extra scale -------------
__global__ void l2norm_kernel(float* __restrict__ x, float scale)
{
    size_t row = blockIdx.x;
    int d = threadIdx.x;  // 128 threads
    float v = x[row * 128 + d];
    float s = v * v;
#pragma unroll
    for (int off = 16; off > 0; off >>= 1) s += __shfl_xor_sync(0xffffffffu, s, off);
    __shared__ float ws[4];
    if ((d & 31) == 0) ws[d >> 5] = s;
    __syncthreads();
    float tot = ws[0] + ws[1] + ws[2] + ws[3];
    x[row * 128 + d] = v * rsqrtf(tot + 1e-6f) * scale;
}

// -------------------- decay0 = exp(-A * softplus(graw+dtb)) ----------------
__global__ void decay_kernel(const float* __restrict__ graw, const float* __restrict__ dt_bias,
                             const float* __restrict__ A_log, float* __restrict__ dec, long total)
{
    long idx = (long)blockIdx.x * blockDim.x + threadIdx.x;
    if (idx >= total) return;
    int ch = (int)(idx % 2048);
    int h = ch >> 7;
    float x = graw[idx] + dt_bias[ch];
    dec[idx] = expf(-expf(A_log[h]) * softplusf_(x));
}

__global__ void sigmoid_kernel(const float* __restrict__ in, float* __restrict__ out, long total)
{
    long idx = (long)blockIdx.x * blockDim.x + threadIdx.x;
    if (idx >= total) return;
    out[idx] = sigmoidf_(in[idx]);
}

// --------------------------- delta-rule microscan --------------------------
__global__ void scan_kernel(const float* __restrict__ qp, const float* __restrict__ kp,
                            const float* __restrict__ vp, const float* __restrict__ dec,
                            const float* __restrict__ beta,
                            const float* __restrict__ dt_bias, const float* __restrict__ A_log,
                            const float* __restrict__ micro_logits,
                            float* __restrict__ o_mix, int T)
{
    const int split = blockIdx.x;
    const int h = blockIdx.y;
    const int b = blockIdx.z;
    const int tid = threadIdx.x;
    const int w = tid >> 5;
    const int c = tid & 31;
    const int vcol = split * 32 + c;

    __shared__ float sq[128], sk[512], sv[512], sdec[128], sdf[128], red[128];
    __shared__ float sb[4], swm[4];

    {
        float dtb = dt_bias[h * 128 + tid];
        float xx = -10000.0f + dtb;
        sdf[tid] = expf(-expf(A_log[h]) * softplusf_(xx));
    }
    if (tid == 0) {
        float m0 = micro_logits[h * 4 + 0], m1 = micro_logits[h * 4 + 1];
        float m2 = micro_logits[h * 4 + 2], m3 = micro_logits[h * 4 + 3];
        float mx = fmaxf(fmaxf(m0, m1), fmaxf(m2, m3));
        float e0 = expf(m0 - mx), e1 = expf(m1 - mx), e2 = expf(m2 - mx), e3 = expf(m3 - mx);
        float inv = 1.f / (e0 + e1 + e2 + e3);
        swm[0] = e0 * inv; swm[1] = e1 * inv; swm[2] = e2 * inv; swm[3] = e3 * inv;
    }

    float S[32];
#pragma unroll
    for (int i = 0; i < 32; i++) S[i] = 0.f;
    __syncthreads();

    for (int t = 0; t < T; t++) {
        const size_t base = ((size_t)(b * T + t) * H_ + h);
        const size_t qoff = base * 128;
        const size_t koff = base * 512;
        sq[tid]   = qp[qoff + tid];
        sdec[tid] = dec[qoff + tid];
#pragma unroll
        for (int j = 0; j < 4; j++) {
            sk[j * 128 + tid] = kp[koff + j * 128 + tid];
            sv[j * 128 + tid] = vp[koff + j * 128 + tid];
        }
        if (tid < 4) sb[tid] = beta[base * 4 + tid];
        __syncthreads();

        float oacc = 0.f;
#pragma unroll
        for (int j = 0; j < 4; j++) {
            const float* kj = &sk[j * 128 + w * 32];
            const float* dd = (j == 0) ? &sdec[w * 32] : &sdf[w * 32];
            float up = 0.f;
#pragma unroll
            for (int i = 0; i < 32; i++) {
                float s = S[i] * dd[i];
                S[i] = s;
                up = fmaf(kj[i], s, up);
            }
            red[tid] = up;
            __syncthreads();
            float u = red[c] + red[32 + c] + red[64 + c] + red[96 + c];
            __syncthreads();
            float coef = sb[j] * (sv[j * 128 + vcol] - u);
            float dj = 0.f;
#pragma unroll
            for (int i = 0; i < 32; i++) {
                float s = fmaf(coef, kj[i], S[i]);
                S[i] = s;
                dj = fmaf(sq[w * 32 + i], s, dj);
            }
            oacc = fmaf(swm[j], dj, oacc);
        }
        red[tid] = oacc;
        __syncthreads();
        if (w == 0) {
            o_mix[qoff + vcol] = red[c] + red[32 + c] + red[64 + c] + red[96 + c];
        }
        __syncthreads();
    }
}

// ------------ output norm: o * rsqrt(mean(o^2)+eps) * w * sigm(gate) -------
__global__ void post_kernel(const float* __restrict__ omix, const float* __restrict__ gate,
                            const float* __restrict__ onw, float* __restrict__ ofin)
{
    size_t row = blockIdx.x;
    int v = threadIdx.x;  // 128
    float o = omix[row * 128 + v];
    float s = o * o;
#pragma unroll
    for (int off = 16; off > 0; off >>= 1) s += __shfl_xor_sync(0xffffffffu, s, off);
    __shared__ float ws[4];
    if ((v & 31) == 0) ws[v >> 5] = s;
    __syncthreads();
    float mean = (ws[0] + ws[1] + ws[2] + ws[3]) * (1.f / 128.f);
    ofin[row * 128 + v] = o * rsqrtf(mean + 1e-5f) * onw[v] * sigmoidf_(gate[row * 128 + v]);
}

// ---------------------------------------------------------------------------
extern "C" void kernel_launch(void* const* d_in, const int* in_sizes, int n_in,
                              void* d_out, int out_size)
{
    const float* x       = (const float*)d_in[0];
    const float* q_proj  = (const float*)d_in[1];
    const float* k_proj  = (const float*)d_in[2];
    const float* v_proj  = (const float*)d_in[3];
    const float* q_convw = (const float*)d_in[4];
    const float* k_convw = (const float*)d_in[5];
    const float* v_convw = (const float*)d_in[6];
    const float* f1_w    = (const float*)d_in[7];
    const float* f2_w    = (const float*)d_in[8];
    const float* b_proj  = (const float*)d_in[9];
    const float* micro   = (const float*)d_in[10];
    const float* A_log   = (const float*)d_in[11];
    const float* dt_bias = (const float*)d_in[12];
    const float* g1_w    = (const float*)d_in[13];
    const float* g2_w    = (const float*)d_in[14];
    const float* g2_b    = (const float*)d_in[15];
    const float* o_normw = (const float*)d_in[16];
    const float* o_proj  = (const float*)d_in[17];
    float* out = (float*)d_out;

    const int T = T_;
    const int BT = in_sizes[0] / HID_;   // B * T
    const int B = BT / T;

    cudaFuncSetAttribute(tgemm_kernel, cudaFuncAttributeMaxDynamicSharedMemorySize, TG_SMEM);

    float *qpre, *kpre, *vpre, *bpre, *f1h, *g1h, *graw, *gate;
    float *qb, *kb, *vb, *decb, *betab, *omix, *ofin;
    cudaGetSymbolAddress((void**)&qpre,  g_qpre);
    cudaGetSymbolAddress((void**)&kpre,  g_kpre);
    cudaGetSymbolAddress((void**)&vpre,  g_vpre);
    cudaGetSymbolAddress((void**)&bpre,  g_bpre);
    cudaGetSymbolAddress((void**)&f1h,   g_f1h);
    cudaGetSymbolAddress((void**)&g1h,   g_g1h);
    cudaGetSymbolAddress((void**)&graw,  g_graw);
    cudaGetSymbolAddress((void**)&gate,  g_gate);
    cudaGetSymbolAddress((void**)&qb,    g_qb);
    cudaGetSymbolAddress((void**)&kb,    g_kb);
    cudaGetSymbolAddress((void**)&vb,    g_vb);
    cudaGetSymbolAddress((void**)&decb,  g_dec);
    cudaGetSymbolAddress((void**)&betab, g_beta);
    cudaGetSymbolAddress((void**)&omix,  g_omix);
    cudaGetSymbolAddress((void**)&ofin,  g_ofin);

    __nv_bfloat16 *xhi, *xlo, *qwh, *qwl, *kwh, *kwl, *vwh, *vwl, *bwh, *bwl;
    __nv_bfloat16 *f1wh, *f1wl, *g1wh, *g1wl, *f2wh, *f2wl, *g2wh, *g2wl, *owh, *owl;
    __nv_bfloat16 *af1h, *af1l, *ag1h, *ag1l, *aofh, *aofl;
    cudaGetSymbolAddress((void**)&xhi,  g_x_hi);   cudaGetSymbolAddress((void**)&xlo,  g_x_lo);
    cudaGetSymbolAddress((void**)&qwh,  g_wq_hi);  cudaGetSymbolAddress((void**)&qwl,  g_wq_lo);
    cudaGetSymbolAddress((void**)&kwh,  g_wk_hi);  cudaGetSymbolAddress((void**)&kwl,  g_wk_lo);
    cudaGetSymbolAddress((void**)&vwh,  g_wv_hi);  cudaGetSymbolAddress((void**)&vwl,  g_wv_lo);
    cudaGetSymbolAddress((void**)&bwh,  g_wb_hi);  cudaGetSymbolAddress((void**)&bwl,  g_wb_lo);
    cudaGetSymbolAddress((void**)&f1wh, g_wf1_hi); cudaGetSymbolAddress((void**)&f1wl, g_wf1_lo);
    cudaGetSymbolAddress((void**)&g1wh, g_wg1_hi); cudaGetSymbolAddress((void**)&g1wl, g_wg1_lo);
    cudaGetSymbolAddress((void**)&f2wh, g_wf2_hi); cudaGetSymbolAddress((void**)&f2wl, g_wf2_lo);
    cudaGetSymbolAddress((void**)&g2wh, g_wg2_hi); cudaGetSymbolAddress((void**)&g2wl, g_wg2_lo);
    cudaGetSymbolAddress((void**)&owh,  g_wo_hi);  cudaGetSymbolAddress((void**)&owl,  g_wo_lo);
    cudaGetSymbolAddress((void**)&af1h, g_af1_hi); cudaGetSymbolAddress((void**)&af1l, g_af1_lo);
    cudaGetSymbolAddress((void**)&ag1h, g_ag1_hi); cudaGetSymbolAddress((void**)&ag1l, g_ag1_lo);
    cudaGetSymbolAddress((void**)&aofh, g_aof_hi); cudaGetSymbolAddress((void**)&aofl, g_aof_lo);

    auto splg = [](long n) { return (unsigned)((n + 255) / 256); };

    // split inputs/weights into bf16 hi/lo
    long nx = (long)BT * HID_;
    split_kernel<<<splg(nx), 256>>>(x, xhi, xlo, nx);
    split_kernel<<<splg((long)KD_ * HID_),  256>>>(q_proj, qwh, qwl, (long)KD_ * HID_);
    split_kernel<<<splg((long)KDR_ * HID_), 256>>>(k_proj, kwh, kwl, (long)KDR_ * HID_);
    split_kernel<<<splg((long)VDR_ * HID_), 256>>>(v_proj, vwh, vwl, (long)VDR_ * HID_);
    split_kernel<<<splg((long)H_ * R_ * HID_), 256>>>(b_proj, bwh, bwl, (long)H_ * R_ * HID_);
    split_kernel<<<splg((long)128 * HID_),  256>>>(f1_w, f1wh, f1wl, (long)128 * HID_);
    split_kernel<<<splg((long)128 * HID_),  256>>>(g1_w, g1wh, g1wl, (long)128 * HID_);
    split_kernel<<<splg((long)KD_ * 128),   256>>>(f2_w, f2wh, f2wl, (long)KD_ * 128);
    split_kernel<<<splg((long)KD_ * 128),   256>>>(g2_w, g2wh, g2wl, (long)KD_ * 128);
    split_kernel<<<splg((long)HID_ * KD_),  256>>>(o_proj, owh, owl, (long)HID_ * KD_);

    auto tg = [&](const __nv_bfloat16* ah, const __nv_bfloat16* al,
                  const __nv_bfloat16* wh, const __nv_bfloat16* wl,
                  float* C, const float* bias, int M, int N, int K) {
        dim3 grid((unsigned)((N + TBN - 1) / TBN), (unsigned)(M / TBM));
        tgemm_kernel<<<grid, 256, TG_SMEM>>>(ah, al, wh, wl, C, bias, M, N, K);
    };

    // projections off x
    tg(xhi, xlo, qwh, qwl, qpre, nullptr, BT, KD_,  HID_);
    tg(xhi, xlo, kwh, kwl, kpre, nullptr, BT, KDR_, HID_);
    tg(xhi, xlo, vwh, vwl, vpre, nullptr, BT, VDR_, HID_);
    tg(xhi, xlo, bwh, bwl, bpre, nullptr, BT, H_ * R_, HID_);
    tg(xhi, xlo, f1wh, f1wl, f1h, nullptr, BT, 128, HID_);
    tg(xhi, xlo, g1wh, g1wl, g1h, nullptr, BT, 128, HID_);
    // low-rank expansions (K=128)
    long nh = (long)BT * 128;
    split_kernel<<<splg(nh), 256>>>(f1h, af1h, af1l, nh);
    split_kernel<<<splg(nh), 256>>>(g1h, ag1h, ag1l, nh);
    tg(af1h, af1l, f2wh, f2wl, graw, nullptr, BT, KD_, 128);
    tg(ag1h, ag1l, g2wh, g2wl, gate, g2_b,    BT, KD_, 128);

    // conv + silu
    long nq = (long)BT * KD_;
    long nk = (long)BT * KDR_;
    conv_silu_kernel<<<splg(nq), 256>>>(qpre, q_convw, qb, KD_,  nq, T);
    conv_silu_kernel<<<splg(nk), 256>>>(kpre, k_convw, kb, KDR_, nk, T);
    conv_silu_kernel<<<splg(nk), 256>>>(vpre, v_convw, vb, VDR_, nk, T);

    // norms + activations
    l2norm_kernel<<<(unsigned)(BT * H_), 128>>>(qb, 0.08838834764831843f);  // D^-0.5
    l2norm_kernel<<<(unsigned)(BT * H_ * R_), 128>>>(kb, 1.0f);
    decay_kernel<<<splg(nq), 256>>>(graw, dt_bias, A_log, decb, nq);
    long nb = (long)BT * H_ * R_;
    sigmoid_kernel<<<splg(nb), 256>>>(bpre, betab, nb);

    // sequential microscan (column-split over DV)
    dim3 sgrid(4, H_, (unsigned)B);
    scan_kernel<<<sgrid, 128>>>(qb, kb, vb, decb, betab, dt_bias, A_log, micro, omix, T);

    // output norm + gate, then o_proj (split-bf16 tensor GEMM)
    post_kernel<<<(unsigned)(BT * H_), 128>>>(omix, gate, o_normw, ofin);
    long no = (long)BT * KD_;
    split_kernel<<<splg(no), 256>>>(ofin, aofh, aofl, no);
    tg(aofh, aofl, owh, owl, out, nullptr, BT, HID_, KD_);
}

// round 11
// speedup vs baseline: 2.5625x; 1.2336x over previous
#include <cuda_runtime.h>
#include <cuda_fp16.h>
#include <math.h>
#include <stdint.h>

#define H_    16
#define D_    128
#define HID_  2048
#define T_    1024
#define B_MAX 2
#define KD_   2048
#define KDR_  8192
#define VDR_  8192
#define CS_   18752
#define COL_Q  0
#define COL_K  2048
#define COL_V  10240
#define COL_B  18432
#define COL_F1 18496

__device__ float g_cproj[B_MAX * T_ * CS_];
__device__ float g_graw [B_MAX * T_ * KD_];
__device__ float g_gate [B_MAX * T_ * KD_];
__device__ float g_qb   [B_MAX * T_ * KD_];
__device__ float g_kb   [B_MAX * T_ * KDR_];
__device__ float g_vb   [B_MAX * T_ * VDR_];
__device__ float g_dec  [B_MAX * T_ * KD_];
__device__ float g_beta [B_MAX * T_ * 64];
__device__ float g_omix [B_MAX * T_ * KD_];

__device__ __align__(16) __half g_combh[CS_ * HID_];
__device__ __align__(16) __half g_combl[CS_ * HID_];
__device__ __align__(16) __half g_wf2h[KD_ * 128];
__device__ __align__(16) __half g_wf2l[KD_ * 128];
__device__ __align__(16) __half g_wg2h[KD_ * 128];
__device__ __align__(16) __half g_wg2l[KD_ * 128];
__device__ __align__(16) __half g_woh[HID_ * KD_];
__device__ __align__(16) __half g_wol[HID_ * KD_];
__device__ __align__(16) __half g_xh[B_MAX * T_ * HID_];
__device__ __align__(16) __half g_f1g1h[B_MAX * T_ * 256];
__device__ __align__(16) __half g_aofh[B_MAX * T_ * KD_];

static __device__ __forceinline__ float sigmoidf_(float x) { return 1.f / (1.f + expf(-x)); }
static __device__ __forceinline__ float softplusf_(float x) { return (x > 20.f) ? x : log1pf(expf(x)); }

// ---------------- weight split: f32 -> fp16 hi + lo (vectorized) -----------
__global__ void splitw_kernel(const float* __restrict__ in,
                              __half* __restrict__ hi, __half* __restrict__ lo, long n4)
{
    long i = (long)blockIdx.x * blockDim.x + threadIdx.x;
    if (i >= n4) return;
    float4 v = reinterpret_cast<const float4*>(in)[i];
    __half hx = __float2half_rn(v.x), hy = __float2half_rn(v.y);
    __half hz = __float2half_rn(v.z), hw = __float2half_rn(v.w);
    reinterpret_cast<__half2*>(hi)[i * 2 + 0] = __halves2half2(hx, hy);
    reinterpret_cast<__half2*>(hi)[i * 2 + 1] = __halves2half2(hz, hw);
    reinterpret_cast<__half2*>(lo)[i * 2 + 0] =
        __halves2half2(__float2half_rn(v.x - __half2float(hx)),
                       __float2half_rn(v.y - __half2float(hy)));
    reinterpret_cast<__half2*>(lo)[i * 2 + 1] =
        __halves2half2(__float2half_rn(v.z - __half2float(hz)),
                       __float2half_rn(v.w - __half2float(hw)));
}

__global__ void cvt16_kernel(const float* __restrict__ in, __half* __restrict__ out, long n4)
{
    long i = (long)blockIdx.x * blockDim.x + threadIdx.x;
    if (i >= n4) return;
    float4 v = reinterpret_cast<const float4*>(in)[i];
    reinterpret_cast<__half2*>(out)[i * 2 + 0] =
        __halves2half2(__float2half_rn(v.x), __float2half_rn(v.y));
    reinterpret_cast<__half2*>(out)[i * 2 + 1] =
        __halves2half2(__float2half_rn(v.z), __float2half_rn(v.w));
}

// extract f1/g1 (256 contiguous cols of cproj) -> compact fp16 [BT,256]
__global__ void cvt_f1g1_kernel(const float* __restrict__ Cp, __half* __restrict__ out, long n)
{
    long i = (long)blockIdx.x * blockDim.x + threadIdx.x;
    if (i >= n) return;
    long r = i >> 8; int c = (int)(i & 255);
    out[i] = __float2half_rn(Cp[r * CS_ + COL_F1 + c]);
}

// ============ fp16 one-sided-split GEMM: C = A @ W^T (+bias) ===============
#define TBM 128
#define TBN 128
#define TBK 64
#define SM_A  0
#define SM_WH 16384
#define SM_WL 32768
#define STAGE_BYTES 49152
#define NSTAGE 4
#define TG_SMEM (NSTAGE * STAGE_BYTES)

static __device__ __forceinline__ uint32_t s2u(const void* p) {
    uint32_t a;
    asm("{ .reg .u64 t; cvta.to.shared.u64 t, %1; cvt.u32.u64 %0, t; }" : "=r"(a) : "l"(p));
    return a;
}
static __device__ __forceinline__ uint32_t swaddr(int row, int colb) {
    return (uint32_t)(row * 128 + (colb ^ ((row & 7) << 4)));
}
static __device__ __forceinline__ void cp16(uint32_t s, const void* g, uint32_t bytes) {
    asm volatile("cp.async.cg.shared.global [%0], [%1], 16, %2;" :: "r"(s), "l"(g), "r"(bytes));
}
static __device__ __forceinline__ void ldsm4(uint32_t* r, uint32_t addr) {
    asm volatile("ldmatrix.sync.aligned.m8n8.x4.shared.b16 {%0,%1,%2,%3}, [%4];"
                 : "=r"(r[0]), "=r"(r[1]), "=r"(r[2]), "=r"(r[3]) : "r"(addr));
}
static __device__ __forceinline__ void mma16816(float* d, const uint32_t* a, const uint32_t* b) {
    asm volatile(
        "mma.sync.aligned.m16n8k16.row.col.f32.f16.f16.f32 "
        "{%0,%1,%2,%3}, {%4,%5,%6,%7}, {%8,%9}, {%0,%1,%2,%3};"
        : "+f"(d[0]), "+f"(d[1]), "+f"(d[2]), "+f"(d[3])
        : "r"(a[0]), "r"(a[1]), "r"(a[2]), "r"(a[3]), "r"(b[0]), "r"(b[1]));
}

static __device__ __forceinline__ void fill_stage(
    uint32_t st, const __half* __restrict__ A,
    const __half* __restrict__ Whi, const __half* __restrict__ Wlo,
    int bm, int bn, int k0, int N, int K, int lda, int tid)
{
#pragma unroll
    for (int it = 0; it < 4; it++) {
        int q = tid + it * 256;
        int row = q >> 3, c16 = q & 7;
        uint32_t so = swaddr(row, c16 * 16);
        cp16(st + SM_A + so, A + (size_t)(bm + row) * lda + k0 + c16 * 8, 16);
    }
#pragma unroll
    for (int it = 0; it < 4; it++) {
        int q = tid + it * 256;
        int row = q >> 3, c16 = q & 7;
        uint32_t so = swaddr(row, c16 * 16);
        int n = bn + row;
        uint32_t vb = (n < N) ? 16u : 0u;
        size_t go = (size_t)((n < N) ? n : 0) * K + k0 + c16 * 8;
        cp16(st + SM_WH + so, Whi + go, vb);
        cp16(st + SM_WL + so, Wlo + go, vb);
    }
    asm volatile("cp.async.commit_group;" ::: "memory");
}

__global__ void __launch_bounds__(256, 1) tgemm_kernel(
    const __half* __restrict__ A, const __half* __restrict__ Whi,
    const __half* __restrict__ Wlo, float* __restrict__ C,
    const float* __restrict__ bias, int M, int N, int K, int lda)
{
    extern __shared__ char smem[];
    const uint32_t sb = s2u(smem);
    const int tid = threadIdx.x;
    const int wid = tid >> 5;
    const int lane = tid & 31;
    const int wm = wid & 1;          // 2 x 64 rows
    const int wn = wid >> 1;         // 4 x 32 cols
    const int bn = blockIdx.x * TBN;
    const int bm = blockIdx.y * TBM;
    const int chunks = K / TBK;

    float acc[4][4][4];
#pragma unroll
    for (int mi = 0; mi < 4; mi++)
#pragma unroll
        for (int ni = 0; ni < 4; ni++)
#pragma unroll
            for (int r = 0; r < 4; r++) acc[mi][ni][r] = 0.f;

    const int pfills = (chunks < NSTAGE - 1) ? chunks : (NSTAGE - 1);
    for (int s = 0; s < pfills; s++)
        fill_stage(sb + (uint32_t)s * STAGE_BYTES, A, Whi, Wlo, bm, bn, s * TBK, N, K, lda, tid);

    const int a_row = wm * 64 + (lane & 15);
    const int a_cg  = (lane >> 4) * 16;
    const int b_grp = lane >> 3;
    const int b_row = wn * 32 + ((b_grp >> 1) << 3) + (lane & 7);
    const int b_cg  = (b_grp & 1) * 16;

    for (int c = 0; c < chunks; c++) {
        int np = chunks - 1 - c; if (np > 2) np = 2;
        if (np == 2)      asm volatile("cp.async.wait_group 2;" ::: "memory");
        else if (np == 1) asm volatile("cp.async.wait_group 1;" ::: "memory");
        else              asm volatile("cp.async.wait_group 0;" ::: "memory");
        __syncthreads();

        if (c + NSTAGE - 1 < chunks)
            fill_stage(sb + (uint32_t)((c + NSTAGE - 1) % NSTAGE) * STAGE_BYTES,
                       A, Whi, Wlo, bm, bn, (c + NSTAGE - 1) * TBK, N, K, lda, tid);

        const uint32_t st = sb + (uint32_t)(c % NSTAGE) * STAGE_BYTES;
#pragma unroll
        for (int k16 = 0; k16 < 4; k16++) {
            const int kb = k16 * 32;
            uint32_t ah[4][4], bh[4][2], bl[4][2];
#pragma unroll
            for (int mi = 0; mi < 4; mi++)
                ldsm4(ah[mi], st + SM_A + swaddr(a_row + mi * 16, kb + a_cg));
#pragma unroll
            for (int p = 0; p < 2; p++) {
                uint32_t th[4], tl[4];
                uint32_t so = swaddr(b_row + p * 16, kb + b_cg);
                ldsm4(th, st + SM_WH + so);
                ldsm4(tl, st + SM_WL + so);
                bh[p * 2][0] = th[0]; bh[p * 2][1] = th[1];
                bh[p * 2 + 1][0] = th[2]; bh[p * 2 + 1][1] = th[3];
                bl[p * 2][0] = tl[0]; bl[p * 2][1] = tl[1];
                bl[p * 2 + 1][0] = tl[2]; bl[p * 2 + 1][1] = tl[3];
            }
#pragma unroll
            for (int mi = 0; mi < 4; mi++)
#pragma unroll
                for (int ni = 0; ni < 4; ni++) {
                    mma16816(acc[mi][ni], ah[mi], bh[ni]);
                    mma16816(acc[mi][ni], ah[mi], bl[ni]);
                }
        }
    }

    const int erow0 = bm + wm * 64 + (lane >> 2);
    const int ecol0 = bn + wn * 32 + (lane & 3) * 2;
#pragma unroll
    for (int mi = 0; mi < 4; mi++) {
#pragma unroll
        for (int ni = 0; ni < 4; ni++) {
            int col = ecol0 + ni * 8;
            if (col < N) {
                float b0 = bias ? bias[col] : 0.f;
                float b1 = bias ? bias[col + 1] : 0.f;
                float2 v0 = make_float2(acc[mi][ni][0] + b0, acc[mi][ni][1] + b1);
                float2 v1 = make_float2(acc[mi][ni][2] + b0, acc[mi][ni][3] + b1);
                *reinterpret_cast<float2*>(C + (size_t)(erow0 + mi * 16) * N + col) = v0;
                *reinterpret_cast<float2*>(C + (size_t)(erow0 + mi * 16 + 8) * N + col) = v1;
            }
        }
    }
}

// -------- fused causal conv + SiLU + per-128 L2 norm (q and k paths) -------
__global__ void convnorm_kernel(const float* __restrict__ Cp, const float* __restrict__ cw,
                                float* __restrict__ out, int col0, int CH, float scale, int T)
{
    const int G = CH >> 7;
    const int bt = blockIdx.x / G;
    const int grp = blockIdx.x % G;
    const int d = threadIdx.x;
    const int c = grp * 128 + d;
    const int t = bt % T;
    const float4 wv = *reinterpret_cast<const float4*>(cw + (size_t)c * 4);
    const float* ip = Cp + (size_t)bt * CS_ + col0 + c;
    float s = ip[0] * wv.w;
    if (t >= 1) s += ip[-(long)CS_] * wv.z;
    if (t >= 2) s += ip[-2L * CS_] * wv.y;
    if (t >= 3) s += ip[-3L * CS_] * wv.x;
    s = s * sigmoidf_(s);
    float ss = s * s;
#pragma unroll
    for (int off = 16; off > 0; off >>= 1) ss += __shfl_xor_sync(0xffffffffu, ss, off);
    __shared__ float ws[4];
    if ((d & 31) == 0) ws[d >> 5] = ss;
    __syncthreads();
    float tot = ws[0] + ws[1] + ws[2] + ws[3];
    out[(size_t)bt * CH + c] = s * rsqrtf(tot + 1e-6f) * scale;
}

// ------------------------- conv + SiLU only (v path) -----------------------
__global__ void conv_silu_kernel(const float* __restrict__ Cp, const float* __restrict__ cw,
                                 float* __restrict__ out, int col0, int CH, long total, int T)
{
    long idx = (long)blockIdx.x * blockDim.x + threadIdx.x;
    if (idx >= total) return;
    int c = (int)(idx % CH);
    long bt = idx / CH;
    int t = (int)(bt % T);
    const float4 wv = *reinterpret_cast<const float4*>(cw + (size_t)c * 4);
    const float* ip = Cp + (size_t)bt * CS_ + col0 + c;
    float s = ip[0] * wv.w;
    if (t >= 1) s += ip[-(long)CS_] * wv.z;
    if (t >= 2) s += ip[-2L * CS_] * wv.y;
    if (t >= 3) s += ip[-3L * CS_] * wv.x;
    out[idx] = s * sigmoidf_(s);
}

__global__ void decay_kernel(const float* __restrict__ graw, const float* __restrict__ dt_bias,
                             const float* __restrict__ A_log, float* __restrict__ dec, long total)
{
    long idx = (long)blockIdx.x * blockDim.x + threadIdx.x;
    if (idx >= total) return;
    int ch = (int)(idx & 2047);
    int h = ch >> 7;
    float x = graw[idx] + dt_bias[ch];
    dec[idx] = expf(-expf(A_log[h]) * softplusf_(x));
}

__global__ void beta_kernel(const float* __restrict__ Cp, float* __restrict__ out, long total)
{
    long idx = (long)blockIdx.x * blockDim.x + threadIdx.x;
    if (idx >= total) return;
    long bt = idx >> 6; int c = (int)(idx & 63);
    out[idx] = sigmoidf_(Cp[bt * CS_ + COL_B + c]);
}

// --------------------------- delta-rule microscan --------------------------
__global__ void scan_kernel(const float* __restrict__ qp, const float* __restrict__ kp,
                            const float* __restrict__ vp, const float* __restrict__ dec,
                            const float* __restrict__ beta,
                            const float* __restrict__ dt_bias, const float* __restrict__ A_log,
                            const float* __restrict__ micro_logits,
                            float* __restrict__ o_mix, int T)
{
    const int split = blockIdx.x;
    const int h = blockIdx.y;
    const int b = blockIdx.z;
    const int tid = threadIdx.x;
    const int w = tid >> 5;
    const int c = tid & 31;
    const int vcol = split * 32 + c;

    __shared__ float sq[128], sk[512], sv[512], sdec[128], sdf[128], red[128];
    __shared__ float sb[4], swm[4];

    {
        float dtb = dt_bias[h * 128 + tid];
        sdf[tid] = expf(-expf(A_log[h]) * softplusf_(-10000.0f + dtb));
    }
    if (tid == 0) {
        float m0 = micro_logits[h * 4 + 0], m1 = micro_logits[h * 4 + 1];
        float m2 = micro_logits[h * 4 + 2], m3 = micro_logits[h * 4 + 3];
        float mx = fmaxf(fmaxf(m0, m1), fmaxf(m2, m3));
        float e0 = expf(m0 - mx), e1 = expf(m1 - mx), e2 = expf(m2 - mx), e3 = expf(m3 - mx);
        float inv = 1.f / (e0 + e1 + e2 + e3);
        swm[0] = e0 * inv; swm[1] = e1 * inv; swm[2] = e2 * inv; swm[3] = e3 * inv;
    }

    float S[32];
#pragma unroll
    for (int i = 0; i < 32; i++) S[i] = 0.f;
    __syncthreads();

    for (int t = 0; t < T; t++) {
        const size_t base = ((size_t)(b * T + t) * H_ + h);
        const size_t qoff = base * 128;
        const size_t koff = base * 512;
        sq[tid]   = qp[qoff + tid];
        sdec[tid] = dec[qoff + tid];
#pragma unroll
        for (int j = 0; j < 4; j++) {
            sk[j * 128 + tid] = kp[koff + j * 128 + tid];
            sv[j * 128 + tid] = vp[koff + j * 128 + tid];
        }
        if (tid < 4) sb[tid] = beta[base * 4 + tid];
        __syncthreads();

        float oacc = 0.f;
#pragma unroll
        for (int j = 0; j < 4; j++) {
            const float* kj = &sk[j * 128 + w * 32];
            const float* dd = (j == 0) ? &sdec[w * 32] : &sdf[w * 32];
            float up = 0.f;
#pragma unroll
            for (int i = 0; i < 32; i++) {
                float s = S[i] * dd[i];
                S[i] = s;
                up = fmaf(kj[i], s, up);
            }
            red[tid] = up;
            __syncthreads();
            float u = red[c] + red[32 + c] + red[64 + c] + red[96 + c];
            __syncthreads();
            float coef = sb[j] * (sv[j * 128 + vcol] - u);
            float dj = 0.f;
#pragma unroll
            for (int i = 0; i < 32; i++) {
                float s = fmaf(coef, kj[i], S[i]);
                S[i] = s;
                dj = fmaf(sq[w * 32 + i], s, dj);
            }
            oacc = fmaf(swm[j], dj, oacc);
        }
        red[tid] = oacc;
        __syncthreads();
        if (w == 0)
            o_mix[qoff + vcol] = red[c] + red[32 + c] + red[64 + c] + red[96 + c];
        __syncthreads();
    }
}

// ------- output norm * gate -> fp16 (feeds o_proj GEMM directly) -----------
__global__ void post_kernel(const float* __restrict__ omix, const float* __restrict__ gate,
                            const float* __restrict__ onw, __half* __restrict__ ofin)
{
    size_t row = blockIdx.x;
    int v = threadIdx.x;
    float o = omix[row * 128 + v];
    float s = o * o;
#pragma unroll
    for (int off = 16; off > 0; off >>= 1) s += __shfl_xor_sync(0xffffffffu, s, off);
    __shared__ float ws[4];
    if ((v & 31) == 0) ws[v >> 5] = s;
    __syncthreads();
    float mean = (ws[0] + ws[1] + ws[2] + ws[3]) * (1.f / 128.f);
    float r = o * rsqrtf(mean + 1e-5f) * onw[v] * sigmoidf_(gate[row * 128 + v]);
    ofin[row * 128 + v] = __float2half_rn(r);
}

// ---------------------------------------------------------------------------
extern "C" void kernel_launch(void* const* d_in, const int* in_sizes, int n_in,
                              void* d_out, int out_size)
{
    const float* x       = (const float*)d_in[0];
    const float* q_proj  = (const float*)d_in[1];
    const float* k_proj  = (const float*)d_in[2];
    const float* v_proj  = (const float*)d_in[3];
    const float* q_convw = (const float*)d_in[4];
    const float* k_convw = (const float*)d_in[5];
    const float* v_convw = (const float*)d_in[6];
    const float* f1_w    = (const float*)d_in[7];
    const float* f2_w    = (const float*)d_in[8];
    const float* b_proj  = (const float*)d_in[9];
    const float* micro   = (const float*)d_in[10];
    const float* A_log   = (const float*)d_in[11];
    const float* dt_bias = (const float*)d_in[12];
    const float* g1_w    = (const float*)d_in[13];
    const float* g2_w    = (const float*)d_in[14];
    const float* g2_b    = (const float*)d_in[15];
    const float* o_normw = (const float*)d_in[16];
    const float* o_proj  = (const float*)d_in[17];
    float* out = (float*)d_out;

    const int T = T_;
    const int BT = in_sizes[0] / HID_;
    const int B = BT / T;

    cudaFuncSetAttribute(tgemm_kernel, cudaFuncAttributeMaxDynamicSharedMemorySize, TG_SMEM);

    float *cproj, *graw, *gate, *qb, *kb, *vb, *decb, *betab, *omix;
    cudaGetSymbolAddress((void**)&cproj, g_cproj);
    cudaGetSymbolAddress((void**)&graw,  g_graw);
    cudaGetSymbolAddress((void**)&gate,  g_gate);
    cudaGetSymbolAddress((void**)&qb,    g_qb);
    cudaGetSymbolAddress((void**)&kb,    g_kb);
    cudaGetSymbolAddress((void**)&vb,    g_vb);
    cudaGetSymbolAddress((void**)&decb,  g_dec);
    cudaGetSymbolAddress((void**)&betab, g_beta);
    cudaGetSymbolAddress((void**)&omix,  g_omix);

    __half *combh, *combl, *f2h, *f2l, *g2h, *g2l, *woh, *wol, *xh, *f1g1h, *aofh;
    cudaGetSymbolAddress((void**)&combh, g_combh);
    cudaGetSymbolAddress((void**)&combl, g_combl);
    cudaGetSymbolAddress((void**)&f2h,   g_wf2h);
    cudaGetSymbolAddress((void**)&f2l,   g_wf2l);
    cudaGetSymbolAddress((void**)&g2h,   g_wg2h);
    cudaGetSymbolAddress((void**)&g2l,   g_wg2l);
    cudaGetSymbolAddress((void**)&woh,   g_woh);
    cudaGetSymbolAddress((void**)&wol,   g_wol);
    cudaGetSymbolAddress((void**)&xh,    g_xh);
    cudaGetSymbolAddress((void**)&f1g1h, g_f1g1h);
    cudaGetSymbolAddress((void**)&aofh,  g_aofh);

    auto g4 = [](long n4) { return (unsigned)((n4 + 255) / 256); };

    // weight splits into merged buffer (rows: q 0, k 2048, v 10240, b 18432, f1 18496, g1 18624)
    splitw_kernel<<<g4((long)KD_  * HID_ / 4), 256>>>(q_proj, combh,                combl,                (long)KD_  * HID_ / 4);
    splitw_kernel<<<g4((long)KDR_ * HID_ / 4), 256>>>(k_proj, combh + (long)COL_K  * HID_, combl + (long)COL_K  * HID_, (long)KDR_ * HID_ / 4);
    splitw_kernel<<<g4((long)VDR_ * HID_ / 4), 256>>>(v_proj, combh + (long)COL_V  * HID_, combl + (long)COL_V  * HID_, (long)VDR_ * HID_ / 4);
    splitw_kernel<<<g4((long)64   * HID_ / 4), 256>>>(b_proj, combh + (long)COL_B  * HID_, combl + (long)COL_B  * HID_, (long)64   * HID_ / 4);
    splitw_kernel<<<g4((long)128  * HID_ / 4), 256>>>(f1_w,   combh + (long)COL_F1 * HID_, combl + (long)COL_F1 * HID_, (long)128  * HID_ / 4);
    splitw_kernel<<<g4((long)128  * HID_ / 4), 256>>>(g1_w,   combh + (long)(COL_F1 + 128) * HID_, combl + (long)(COL_F1 + 128) * HID_, (long)128 * HID_ / 4);
    splitw_kernel<<<g4((long)KD_ * 128 / 4),  256>>>(f2_w, f2h, f2l, (long)KD_ * 128 / 4);
    splitw_kernel<<<g4((long)KD_ * 128 / 4),  256>>>(g2_w, g2h, g2l, (long)KD_ * 128 / 4);
    splitw_kernel<<<g4((long)HID_ * KD_ / 4), 256>>>(o_proj, woh, wol, (long)HID_ * KD_ / 4);
    cvt16_kernel<<<g4((long)BT * HID_ / 4), 256>>>(x, xh, (long)BT * HID_ / 4);

    auto tg = [&](const __half* a, const __half* wh, const __half* wl,
                  float* C, const float* bias, int M, int N, int K, int lda) {
        dim3 grid((unsigned)((N + TBN - 1) / TBN), (unsigned)(M / TBM));
        tgemm_kernel<<<grid, 256, TG_SMEM>>>(a, wh, wl, C, bias, M, N, K, lda);
    };

    // merged projection GEMM (q|k|v|b|f1|g1)
    tg(xh, combh, combl, cproj, nullptr, BT, CS_, HID_, HID_);

    // low-rank expansions off f1/g1 (K=128)
    cvt_f1g1_kernel<<<g4((long)BT * 256 / 1), 256>>>(cproj, f1g1h, (long)BT * 256);
    tg(f1g1h,       f2h, f2l, graw, nullptr, BT, KD_, 128, 256);
    tg(f1g1h + 128, g2h, g2l, gate, g2_b,    BT, KD_, 128, 256);

    // conv+silu(+l2norm) from merged proj
    convnorm_kernel<<<(unsigned)(BT * (KD_ >> 7)),  128>>>(cproj, q_convw, qb, COL_Q, KD_,  0.08838834764831843f, T);
    convnorm_kernel<<<(unsigned)(BT * (KDR_ >> 7)), 128>>>(cproj, k_convw, kb, COL_K, KDR_, 1.0f, T);
    long nv = (long)BT * VDR_;
    conv_silu_kernel<<<(unsigned)((nv + 255) / 256), 256>>>(cproj, v_convw, vb, COL_V, VDR_, nv, T);

    long nq = (long)BT * KD_;
    decay_kernel<<<(unsigned)((nq + 255) / 256), 256>>>(graw, dt_bias, A_log, decb, nq);
    long nb = (long)BT * 64;
    beta_kernel<<<(unsigned)((nb + 255) / 256), 256>>>(cproj, betab, nb);

    // sequential microscan
    dim3 sgrid(4, H_, (unsigned)B);
    scan_kernel<<<sgrid, 128>>>(qb, kb, vb, decb, betab, dt_bias, A_log, micro, omix, T);

    // output norm + gate -> fp16, then o_proj
    post_kernel<<<(unsigned)(BT * H_), 128>>>(omix, gate, o_normw, aofh);
    tg(aofh, woh, wol, out, nullptr, BT, HID_, KD_, KD_);
}

// round 12
// speedup vs baseline: 3.9413x; 1.5381x over previous
#include <cuda_runtime.h>
#include <cuda_fp16.h>
#include <math.h>
#include <stdint.h>

#define H_    16
#define HID_  2048
#define T_    1024
#define B_MAX 2
#define KD_   2048
#define KDR_  8192
#define VDR_  8192
#define CS_   18752
#define COL_Q  0
#define COL_K  2048
#define COL_V  10240
#define COL_B  18432
#define COL_F1 18496

__device__ float g_cproj[B_MAX * T_ * CS_];
__device__ float g_graw [B_MAX * T_ * KD_];
__device__ float g_gate [B_MAX * T_ * KD_];
__device__ float g_qb   [B_MAX * T_ * KD_];
__device__ float g_kb   [B_MAX * T_ * KDR_];
__device__ float g_vb   [B_MAX * T_ * VDR_];
__device__ float g_dec  [B_MAX * T_ * KD_];
__device__ float g_beta [B_MAX * T_ * 64];
__device__ float g_omix [B_MAX * T_ * KD_];

__device__ __align__(16) __half g_combh[CS_ * HID_];
__device__ __align__(16) __half g_combl[CS_ * HID_];
__device__ __align__(16) __half g_wf2h[KD_ * 128];
__device__ __align__(16) __half g_wf2l[KD_ * 128];
__device__ __align__(16) __half g_wg2h[KD_ * 128];
__device__ __align__(16) __half g_wg2l[KD_ * 128];
__device__ __align__(16) __half g_woh[HID_ * KD_];
__device__ __align__(16) __half g_wol[HID_ * KD_];
__device__ __align__(16) __half g_xh[B_MAX * T_ * HID_];
__device__ __align__(16) __half g_f1g1h[B_MAX * T_ * 256];
__device__ __align__(16) __half g_aofh[B_MAX * T_ * KD_];

static __device__ __forceinline__ float sigmoidf_(float x) { return 1.f / (1.f + expf(-x)); }
static __device__ __forceinline__ float softplusf_(float x) { return (x > 20.f) ? x : log1pf(expf(x)); }

// ---------------------------- packed f32x2 helpers -------------------------
typedef unsigned long long u64;
static __device__ __forceinline__ u64 pk2(float lo, float hi) {
    u64 r; asm("mov.b64 %0, {%1, %2};" : "=l"(r) : "f"(lo), "f"(hi)); return r;
}
static __device__ __forceinline__ void upk2(u64 v, float& lo, float& hi) {
    asm("mov.b64 {%0, %1}, %2;" : "=f"(lo), "=f"(hi) : "l"(v));
}
static __device__ __forceinline__ u64 f2mul(u64 a, u64 b) {
    u64 r; asm("mul.rn.f32x2 %0, %1, %2;" : "=l"(r) : "l"(a), "l"(b)); return r;
}
static __device__ __forceinline__ u64 f2fma(u64 a, u64 b, u64 c) {
    u64 r; asm("fma.rn.f32x2 %0, %1, %2, %3;" : "=l"(r) : "l"(a), "l"(b), "l"(c)); return r;
}
static __device__ __forceinline__ u64 f2add(u64 a, u64 b) {
    u64 r; asm("add.rn.f32x2 %0, %1, %2;" : "=l"(r) : "l"(a), "l"(b)); return r;
}

// ---------------- weight split: f32 -> fp16 hi + lo (vectorized) -----------
__global__ void splitw_kernel(const float* __restrict__ in,
                              __half* __restrict__ hi, __half* __restrict__ lo, long n4)
{
    long i = (long)blockIdx.x * blockDim.x + threadIdx.x;
    if (i >= n4) return;
    float4 v = reinterpret_cast<const float4*>(in)[i];
    __half hx = __float2half_rn(v.x), hy = __float2half_rn(v.y);
    __half hz = __float2half_rn(v.z), hw = __float2half_rn(v.w);
    reinterpret_cast<__half2*>(hi)[i * 2 + 0] = __halves2half2(hx, hy);
    reinterpret_cast<__half2*>(hi)[i * 2 + 1] = __halves2half2(hz, hw);
    reinterpret_cast<__half2*>(lo)[i * 2 + 0] =
        __halves2half2(__float2half_rn(v.x - __half2float(hx)),
                       __float2half_rn(v.y - __half2float(hy)));
    reinterpret_cast<__half2*>(lo)[i * 2 + 1] =
        __halves2half2(__float2half_rn(v.z - __half2float(hz)),
                       __float2half_rn(v.w - __half2float(hw)));
}

__global__ void cvt16_kernel(const float* __restrict__ in, __half* __restrict__ out, long n4)
{
    long i = (long)blockIdx.x * blockDim.x + threadIdx.x;
    if (i >= n4) return;
    float4 v = reinterpret_cast<const float4*>(in)[i];
    reinterpret_cast<__half2*>(out)[i * 2 + 0] =
        __halves2half2(__float2half_rn(v.x), __float2half_rn(v.y));
    reinterpret_cast<__half2*>(out)[i * 2 + 1] =
        __halves2half2(__float2half_rn(v.z), __float2half_rn(v.w));
}

__global__ void cvt_f1g1_kernel(const float* __restrict__ Cp, __half* __restrict__ out, long n)
{
    long i = (long)blockIdx.x * blockDim.x + threadIdx.x;
    if (i >= n) return;
    long r = i >> 8; int c = (int)(i & 255);
    out[i] = __float2half_rn(Cp[r * CS_ + COL_F1 + c]);
}

// ============ fp16 one-sided-split GEMM: C = A @ W^T (+bias) ===============
#define TBM 128
#define TBN 128
#define TBK 64
#define SM_A  0
#define SM_WH 16384
#define SM_WL 32768
#define STAGE_BYTES 49152
#define NSTAGE 4
#define TG_SMEM (NSTAGE * STAGE_BYTES)

static __device__ __forceinline__ uint32_t s2u(const void* p) {
    uint32_t a;
    asm("{ .reg .u64 t; cvta.to.shared.u64 t, %1; cvt.u32.u64 %0, t; }" : "=r"(a) : "l"(p));
    return a;
}
static __device__ __forceinline__ uint32_t swaddr(int row, int colb) {
    return (uint32_t)(row * 128 + (colb ^ ((row & 7) << 4)));
}
static __device__ __forceinline__ void cp16(uint32_t s, const void* g, uint32_t bytes) {
    asm volatile("cp.async.cg.shared.global [%0], [%1], 16, %2;" :: "r"(s), "l"(g), "r"(bytes));
}
static __device__ __forceinline__ void ldsm4(uint32_t* r, uint32_t addr) {
    asm volatile("ldmatrix.sync.aligned.m8n8.x4.shared.b16 {%0,%1,%2,%3}, [%4];"
                 : "=r"(r[0]), "=r"(r[1]), "=r"(r[2]), "=r"(r[3]) : "r"(addr));
}
static __device__ __forceinline__ void mma16816(float* d, const uint32_t* a, const uint32_t* b) {
    asm volatile(
        "mma.sync.aligned.m16n8k16.row.col.f32.f16.f16.f32 "
        "{%0,%1,%2,%3}, {%4,%5,%6,%7}, {%8,%9}, {%0,%1,%2,%3};"
        : "+f"(d[0]), "+f"(d[1]), "+f"(d[2]), "+f"(d[3])
        : "r"(a[0]), "r"(a[1]), "r"(a[2]), "r"(a[3]), "r"(b[0]), "r"(b[1]));
}

static __device__ __forceinline__ void fill_stage(
    uint32_t st, const __half* __restrict__ A,
    const __half* __restrict__ Whi, const __half* __restrict__ Wlo,
    int bm, int bn, int k0, int N, int K, int lda, int tid)
{
#pragma unroll
    for (int it = 0; it < 4; it++) {
        int q = tid + it * 256;
        int row = q >> 3, c16 = q & 7;
        uint32_t so = swaddr(row, c16 * 16);
        cp16(st + SM_A + so, A + (size_t)(bm + row) * lda + k0 + c16 * 8, 16);
    }
#pragma unroll
    for (int it = 0; it < 4; it++) {
        int q = tid + it * 256;
        int row = q >> 3, c16 = q & 7;
        uint32_t so = swaddr(row, c16 * 16);
        int n = bn + row;
        uint32_t vb = (n < N) ? 16u : 0u;
        size_t go = (size_t)((n < N) ? n : 0) * K + k0 + c16 * 8;
        cp16(st + SM_WH + so, Whi + go, vb);
        cp16(st + SM_WL + so, Wlo + go, vb);
    }
    asm volatile("cp.async.commit_group;" ::: "memory");
}

__global__ void __launch_bounds__(256, 1) tgemm_kernel(
    const __half* __restrict__ A, const __half* __restrict__ Whi,
    const __half* __restrict__ Wlo, float* __restrict__ C,
    const float* __restrict__ bias, int M, int N, int K, int lda)
{
    extern __shared__ char smem[];
    const uint32_t sb = s2u(smem);
    const int tid = threadIdx.x;
    const int wid = tid >> 5;
    const int lane = tid & 31;
    const int wm = wid & 1;
    const int wn = wid >> 1;
    const int bn = blockIdx.x * TBN;
    const int bm = blockIdx.y * TBM;
    const int chunks = K / TBK;

    float acc[4][4][4];
#pragma unroll
    for (int mi = 0; mi < 4; mi++)
#pragma unroll
        for (int ni = 0; ni < 4; ni++)
#pragma unroll
            for (int r = 0; r < 4; r++) acc[mi][ni][r] = 0.f;

    const int pfills = (chunks < NSTAGE - 1) ? chunks : (NSTAGE - 1);
    for (int s = 0; s < pfills; s++)
        fill_stage(sb + (uint32_t)s * STAGE_BYTES, A, Whi, Wlo, bm, bn, s * TBK, N, K, lda, tid);

    const int a_row = wm * 64 + (lane & 15);
    const int a_cg  = (lane >> 4) * 16;
    const int b_grp = lane >> 3;
    const int b_row = wn * 32 + ((b_grp >> 1) << 3) + (lane & 7);
    const int b_cg  = (b_grp & 1) * 16;

    for (int c = 0; c < chunks; c++) {
        int np = chunks - 1 - c; if (np > 2) np = 2;
        if (np == 2)      asm volatile("cp.async.wait_group 2;" ::: "memory");
        else if (np == 1) asm volatile("cp.async.wait_group 1;" ::: "memory");
        else              asm volatile("cp.async.wait_group 0;" ::: "memory");
        __syncthreads();

        if (c + NSTAGE - 1 < chunks)
            fill_stage(sb + (uint32_t)((c + NSTAGE - 1) % NSTAGE) * STAGE_BYTES,
                       A, Whi, Wlo, bm, bn, (c + NSTAGE - 1) * TBK, N, K, lda, tid);

        const uint32_t st = sb + (uint32_t)(c % NSTAGE) * STAGE_BYTES;
#pragma unroll
        for (int k16 = 0; k16 < 4; k16++) {
            const int kb = k16 * 32;
            uint32_t ah[4][4], bh[4][2], bl[4][2];
#pragma unroll
            for (int mi = 0; mi < 4; mi++)
                ldsm4(ah[mi], st + SM_A + swaddr(a_row + mi * 16, kb + a_cg));
#pragma unroll
            for (int p = 0; p < 2; p++) {
                uint32_t th[4], tl[4];
                uint32_t so = swaddr(b_row + p * 16, kb + b_cg);
                ldsm4(th, st + SM_WH + so);
                ldsm4(tl, st + SM_WL + so);
                bh[p * 2][0] = th[0]; bh[p * 2][1] = th[1];
                bh[p * 2 + 1][0] = th[2]; bh[p * 2 + 1][1] = th[3];
                bl[p * 2][0] = tl[0]; bl[p * 2][1] = tl[1];
                bl[p * 2 + 1][0] = tl[2]; bl[p * 2 + 1][1] = tl[3];
            }
#pragma unroll
            for (int mi = 0; mi < 4; mi++)
#pragma unroll
                for (int ni = 0; ni < 4; ni++) {
                    mma16816(acc[mi][ni], ah[mi], bh[ni]);
                    mma16816(acc[mi][ni], ah[mi], bl[ni]);
                }
        }
    }

    const int erow0 = bm + wm * 64 + (lane >> 2);
    const int ecol0 = bn + wn * 32 + (lane & 3) * 2;
#pragma unroll
    for (int mi = 0; mi < 4; mi++) {
#pragma unroll
        for (int ni = 0; ni < 4; ni++) {
            int col = ecol0 + ni * 8;
            if (col < N) {
                float b0 = bias ? bias[col] : 0.f;
                float b1 = bias ? bias[col + 1] : 0.f;
                float2 v0 = make_float2(acc[mi][ni][0] + b0, acc[mi][ni][1] + b1);
                float2 v1 = make_float2(acc[mi][ni][2] + b0, acc[mi][ni][3] + b1);
                *reinterpret_cast<float2*>(C + (size_t)(erow0 + mi * 16) * N + col) = v0;
                *reinterpret_cast<float2*>(C + (size_t)(erow0 + mi * 16 + 8) * N + col) = v1;
            }
        }
    }
}

// -------- fused causal conv + SiLU + per-128 L2 norm (q and k paths) -------
__global__ void convnorm_kernel(const float* __restrict__ Cp, const float* __restrict__ cw,
                                float* __restrict__ out, int col0, int CH, float scale, int T)
{
    const int G = CH >> 7;
    const int bt = blockIdx.x / G;
    const int grp = blockIdx.x % G;
    const int d = threadIdx.x;
    const int c = grp * 128 + d;
    const int t = bt % T;
    const float4 wv = *reinterpret_cast<const float4*>(cw + (size_t)c * 4);
    const float* ip = Cp + (size_t)bt * CS_ + col0 + c;
    float s = ip[0] * wv.w;
    if (t >= 1) s += ip[-(long)CS_] * wv.z;
    if (t >= 2) s += ip[-2L * CS_] * wv.y;
    if (t >= 3) s += ip[-3L * CS_] * wv.x;
    s = s * sigmoidf_(s);
    float ss = s * s;
#pragma unroll
    for (int off = 16; off > 0; off >>= 1) ss += __shfl_xor_sync(0xffffffffu, ss, off);
    __shared__ float ws[4];
    if ((d & 31) == 0) ws[d >> 5] = ss;
    __syncthreads();
    float tot = ws[0] + ws[1] + ws[2] + ws[3];
    out[(size_t)bt * CH + c] = s * rsqrtf(tot + 1e-6f) * scale;
}

__global__ void conv_silu_kernel(const float* __restrict__ Cp, const float* __restrict__ cw,
                                 float* __restrict__ out, int col0, int CH, long total, int T)
{
    long idx = (long)blockIdx.x * blockDim.x + threadIdx.x;
    if (idx >= total) return;
    int c = (int)(idx % CH);
    long bt = idx / CH;
    int t = (int)(bt % T);
    const float4 wv = *reinterpret_cast<const float4*>(cw + (size_t)c * 4);
    const float* ip = Cp + (size_t)bt * CS_ + col0 + c;
    float s = ip[0] * wv.w;
    if (t >= 1) s += ip[-(long)CS_] * wv.z;
    if (t >= 2) s += ip[-2L * CS_] * wv.y;
    if (t >= 3) s += ip[-3L * CS_] * wv.x;
    out[idx] = s * sigmoidf_(s);
}

__global__ void decay_kernel(const float* __restrict__ graw, const float* __restrict__ dt_bias,
                             const float* __restrict__ A_log, float* __restrict__ dec, long total)
{
    long idx = (long)blockIdx.x * blockDim.x + threadIdx.x;
    if (idx >= total) return;
    int ch = (int)(idx & 2047);
    int h = ch >> 7;
    float x = graw[idx] + dt_bias[ch];
    dec[idx] = expf(-expf(A_log[h]) * softplusf_(x));
}

__global__ void beta_kernel(const float* __restrict__ Cp, float* __restrict__ out, long total)
{
    long idx = (long)blockIdx.x * blockDim.x + threadIdx.x;
    if (idx >= total) return;
    long bt = idx >> 6; int c = (int)(idx & 63);
    out[idx] = sigmoidf_(Cp[bt * CS_ + COL_B + c]);
}

// ----------------- delta-rule microscan (packed f32x2 FFMA2) ---------------
// grid (4, H, B); block 128; warp w owns d in [32w,32w+32) as 16 f32x2;
// lane c owns column split*32+c.
__global__ void __launch_bounds__(128, 1) scan_kernel(
    const float* __restrict__ qp, const float* __restrict__ kp,
    const float* __restrict__ vp, const float* __restrict__ dec,
    const float* __restrict__ beta,
    const float* __restrict__ dt_bias, const float* __restrict__ A_log,
    const float* __restrict__ micro_logits,
    float* __restrict__ o_mix, int T)
{
    const int split = blockIdx.x;
    const int h = blockIdx.y;
    const int b = blockIdx.z;
    const int tid = threadIdx.x;
    const int w = tid >> 5;
    const int c = tid & 31;
    const int vcol = split * 32 + c;

    __shared__ __align__(8) float sq[128], sdec[128], sk[512], sv[512];
    __shared__ float red[2][128], ored[128], sb4[4];

    const float A = expf(A_log[h]);
    u64 sdf2[16], swm2[4];
#pragma unroll
    for (int i = 0; i < 16; i++) {
        int d0 = w * 32 + 2 * i;
        float f0 = expf(-A * softplusf_(-10000.0f + dt_bias[h * 128 + d0]));
        float f1 = expf(-A * softplusf_(-10000.0f + dt_bias[h * 128 + d0 + 1]));
        sdf2[i] = pk2(f0, f1);
    }
    {
        float m0 = micro_logits[h * 4 + 0], m1 = micro_logits[h * 4 + 1];
        float m2 = micro_logits[h * 4 + 2], m3 = micro_logits[h * 4 + 3];
        float mx = fmaxf(fmaxf(m0, m1), fmaxf(m2, m3));
        float e0 = expf(m0 - mx), e1 = expf(m1 - mx), e2 = expf(m2 - mx), e3 = expf(m3 - mx);
        float inv = 1.f / (e0 + e1 + e2 + e3);
        swm2[0] = pk2(e0 * inv, e0 * inv); swm2[1] = pk2(e1 * inv, e1 * inv);
        swm2[2] = pk2(e2 * inv, e2 * inv); swm2[3] = pk2(e3 * inv, e3 * inv);
    }

    u64 S2[16];
#pragma unroll
    for (int i = 0; i < 16; i++) S2[i] = pk2(0.f, 0.f);

    // staging layout (640 float2): q 0-63 | dec 64-127 | k 128-383 | v 384-639
    {
        size_t base0 = ((size_t)(b * T) * H_ + h);
        size_t q0 = base0 * 128, k0 = base0 * 512;
#pragma unroll
        for (int i = 0; i < 5; i++) {
            int fl = tid + i * 128;
            const float2* src;
            float2* dst;
            if (fl < 64)       { src = (const float2*)(qp  + q0) + fl;        dst = (float2*)sq   + fl; }
            else if (fl < 128) { src = (const float2*)(dec + q0) + (fl - 64); dst = (float2*)sdec + (fl - 64); }
            else if (fl < 384) { src = (const float2*)(kp  + k0) + (fl - 128);dst = (float2*)sk   + (fl - 128); }
            else               { src = (const float2*)(vp  + k0) + (fl - 384);dst = (float2*)sv   + (fl - 384); }
            *dst = *src;
        }
        if (tid < 4) sb4[tid] = beta[base0 * 4 + tid];
    }
    __syncthreads();

    for (int t = 0; t < T; t++) {
        // prefetch t+1 into registers
        float2 pf[5]; float pfb = 0.f;
        {
            int tn = (t + 1 < T) ? (t + 1) : t;
            size_t basen = ((size_t)(b * T + tn) * H_ + h);
            size_t qn = basen * 128, kn = basen * 512;
#pragma unroll
            for (int i = 0; i < 5; i++) {
                int fl = tid + i * 128;
                const float2* src;
                if (fl < 64)       src = (const float2*)(qp  + qn) + fl;
                else if (fl < 128) src = (const float2*)(dec + qn) + (fl - 64);
                else if (fl < 384) src = (const float2*)(kp  + kn) + (fl - 128);
                else               src = (const float2*)(vp  + kn) + (fl - 384);
                pf[i] = *src;
            }
            if (tid < 4) pfb = beta[basen * 4 + tid];
        }

        // cache q for this t
        u64 q2[16];
        {
            const float2* qsp = (const float2*)sq + w * 16;
#pragma unroll
            for (int i = 0; i < 16; i++) { float2 v = qsp[i]; q2[i] = pk2(v.x, v.y); }
        }

        u64 oacc2 = pk2(0.f, 0.f);
#pragma unroll
        for (int j = 0; j < 4; j++) {
            const float2* ksp = (const float2*)(sk + j * 128) + w * 16;
            u64 k2[16];
#pragma unroll
            for (int i = 0; i < 16; i++) { float2 v = ksp[i]; k2[i] = pk2(v.x, v.y); }

            u64 ua = pk2(0.f, 0.f), ub = pk2(0.f, 0.f);
            if (j == 0) {
                const float2* dsp = (const float2*)sdec + w * 16;
#pragma unroll
                for (int i = 0; i < 16; i++) {
                    float2 dv = dsp[i];
                    S2[i] = f2mul(S2[i], pk2(dv.x, dv.y));
                    if (i & 1) ub = f2fma(k2[i], S2[i], ub);
                    else       ua = f2fma(k2[i], S2[i], ua);
                }
            } else {
#pragma unroll
                for (int i = 0; i < 16; i++) {
                    S2[i] = f2mul(S2[i], sdf2[i]);
                    if (i & 1) ub = f2fma(k2[i], S2[i], ub);
                    else       ua = f2fma(k2[i], S2[i], ua);
                }
            }
            float ux, uy; upk2(f2add(ua, ub), ux, uy);
            red[j & 1][tid] = ux + uy;
            __syncthreads();
            float u = red[j & 1][c] + red[j & 1][32 + c] + red[j & 1][64 + c] + red[j & 1][96 + c];
            float coef = sb4[j] * (sv[j * 128 + vcol] - u);
            u64 c2 = pk2(coef, coef);

            u64 da = pk2(0.f, 0.f), db = pk2(0.f, 0.f);
#pragma unroll
            for (int i = 0; i < 16; i++) {
                S2[i] = f2fma(c2, k2[i], S2[i]);
                if (i & 1) db = f2fma(q2[i], S2[i], db);
                else       da = f2fma(q2[i], S2[i], da);
            }
            oacc2 = f2fma(swm2[j], f2add(da, db), oacc2);
        }

        float ox, oy; upk2(oacc2, ox, oy);
        ored[tid] = ox + oy;
        __syncthreads();
        if (w == 0)
            o_mix[((size_t)(b * T + t) * H_ + h) * 128 + vcol] =
                ored[c] + ored[32 + c] + ored[64 + c] + ored[96 + c];
        // stage t+1 (disjoint from ored; reads of this t's sk/sv done before ored sync)
#pragma unroll
        for (int i = 0; i < 5; i++) {
            int fl = tid + i * 128;
            float2* dst;
            if (fl < 64)       dst = (float2*)sq   + fl;
            else if (fl < 128) dst = (float2*)sdec + (fl - 64);
            else if (fl < 384) dst = (float2*)sk   + (fl - 128);
            else               dst = (float2*)sv   + (fl - 384);
            *dst = pf[i];
        }
        if (tid < 4) sb4[tid] = pfb;
        __syncthreads();
    }
}

// ------- output norm * gate -> fp16 (feeds o_proj GEMM directly) -----------
__global__ void post_kernel(const float* __restrict__ omix, const float* __restrict__ gate,
                            const float* __restrict__ onw, __half* __restrict__ ofin)
{
    size_t row = blockIdx.x;
    int v = threadIdx.x;
    float o = omix[row * 128 + v];
    float s = o * o;
#pragma unroll
    for (int off = 16; off > 0; off >>= 1) s += __shfl_xor_sync(0xffffffffu, s, off);
    __shared__ float ws[4];
    if ((v & 31) == 0) ws[v >> 5] = s;
    __syncthreads();
    float mean = (ws[0] + ws[1] + ws[2] + ws[3]) * (1.f / 128.f);
    float r = o * rsqrtf(mean + 1e-5f) * onw[v] * sigmoidf_(gate[row * 128 + v]);
    ofin[row * 128 + v] = __float2half_rn(r);
}

// ---------------------------------------------------------------------------
extern "C" void kernel_launch(void* const* d_in, const int* in_sizes, int n_in,
                              void* d_out, int out_size)
{
    const float* x       = (const float*)d_in[0];
    const float* q_proj  = (const float*)d_in[1];
    const float* k_proj  = (const float*)d_in[2];
    const float* v_proj  = (const float*)d_in[3];
    const float* q_convw = (const float*)d_in[4];
    const float* k_convw = (const float*)d_in[5];
    const float* v_convw = (const float*)d_in[6];
    const float* f1_w    = (const float*)d_in[7];
    const float* f2_w    = (const float*)d_in[8];
    const float* b_proj  = (const float*)d_in[9];
    const float* micro   = (const float*)d_in[10];
    const float* A_log   = (const float*)d_in[11];
    const float* dt_bias = (const float*)d_in[12];
    const float* g1_w    = (const float*)d_in[13];
    const float* g2_w    = (const float*)d_in[14];
    const float* g2_b    = (const float*)d_in[15];
    const float* o_normw = (const float*)d_in[16];
    const float* o_proj  = (const float*)d_in[17];
    float* out = (float*)d_out;

    const int T = T_;
    const int BT = in_sizes[0] / HID_;
    const int B = BT / T;

    cudaFuncSetAttribute(tgemm_kernel, cudaFuncAttributeMaxDynamicSharedMemorySize, TG_SMEM);

    float *cproj, *graw, *gate, *qb, *kb, *vb, *decb, *betab, *omix;
    cudaGetSymbolAddress((void**)&cproj, g_cproj);
    cudaGetSymbolAddress((void**)&graw,  g_graw);
    cudaGetSymbolAddress((void**)&gate,  g_gate);
    cudaGetSymbolAddress((void**)&qb,    g_qb);
    cudaGetSymbolAddress((void**)&kb,    g_kb);
    cudaGetSymbolAddress((void**)&vb,    g_vb);
    cudaGetSymbolAddress((void**)&decb,  g_dec);
    cudaGetSymbolAddress((void**)&betab, g_beta);
    cudaGetSymbolAddress((void**)&omix,  g_omix);

    __half *combh, *combl, *f2h, *f2l, *g2h, *g2l, *woh, *wol, *xh, *f1g1h, *aofh;
    cudaGetSymbolAddress((void**)&combh, g_combh);
    cudaGetSymbolAddress((void**)&combl, g_combl);
    cudaGetSymbolAddress((void**)&f2h,   g_wf2h);
    cudaGetSymbolAddress((void**)&f2l,   g_wf2l);
    cudaGetSymbolAddress((void**)&g2h,   g_wg2h);
    cudaGetSymbolAddress((void**)&g2l,   g_wg2l);
    cudaGetSymbolAddress((void**)&woh,   g_woh);
    cudaGetSymbolAddress((void**)&wol,   g_wol);
    cudaGetSymbolAddress((void**)&xh,    g_xh);
    cudaGetSymbolAddress((void**)&f1g1h, g_f1g1h);
    cudaGetSymbolAddress((void**)&aofh,  g_aofh);

    auto g4 = [](long n4) { return (unsigned)((n4 + 255) / 256); };

    splitw_kernel<<<g4((long)KD_  * HID_ / 4), 256>>>(q_proj, combh,                combl,                (long)KD_  * HID_ / 4);
    splitw_kernel<<<g4((long)KDR_ * HID_ / 4), 256>>>(k_proj, combh + (long)COL_K  * HID_, combl + (long)COL_K  * HID_, (long)KDR_ * HID_ / 4);
    splitw_kernel<<<g4((long)VDR_ * HID_ / 4), 256>>>(v_proj, combh + (long)COL_V  * HID_, combl + (long)COL_V  * HID_, (long)VDR_ * HID_ / 4);
    splitw_kernel<<<g4((long)64   * HID_ / 4), 256>>>(b_proj, combh + (long)COL_B  * HID_, combl + (long)COL_B  * HID_, (long)64   * HID_ / 4);
    splitw_kernel<<<g4((long)128  * HID_ / 4), 256>>>(f1_w,   combh + (long)COL_F1 * HID_, combl + (long)COL_F1 * HID_, (long)128  * HID_ / 4);
    splitw_kernel<<<g4((long)128  * HID_ / 4), 256>>>(g1_w,   combh + (long)(COL_F1 + 128) * HID_, combl + (long)(COL_F1 + 128) * HID_, (long)128 * HID_ / 4);
    splitw_kernel<<<g4((long)KD_ * 128 / 4),  256>>>(f2_w, f2h, f2l, (long)KD_ * 128 / 4);
    splitw_kernel<<<g4((long)KD_ * 128 / 4),  256>>>(g2_w, g2h, g2l, (long)KD_ * 128 / 4);
    splitw_kernel<<<g4((long)HID_ * KD_ / 4), 256>>>(o_proj, woh, wol, (long)HID_ * KD_ / 4);
    cvt16_kernel<<<g4((long)BT * HID_ / 4), 256>>>(x, xh, (long)BT * HID_ / 4);

    auto tg = [&](const __half* a, const __half* wh, const __half* wl,
                  float* C, const float* bias, int M, int N, int K, int lda) {
        dim3 grid((unsigned)((N + TBN - 1) / TBN), (unsigned)(M / TBM));
        tgemm_kernel<<<grid, 256, TG_SMEM>>>(a, wh, wl, C, bias, M, N, K, lda);
    };

    // merged projection GEMM (q|k|v|b|f1|g1)
    tg(xh, combh, combl, cproj, nullptr, BT, CS_, HID_, HID_);

    // low-rank expansions off f1/g1 (K=128)
    cvt_f1g1_kernel<<<g4((long)BT * 256), 256>>>(cproj, f1g1h, (long)BT * 256);
    tg(f1g1h,       f2h, f2l, graw, nullptr, BT, KD_, 128, 256);
    tg(f1g1h + 128, g2h, g2l, gate, g2_b,    BT, KD_, 128, 256);

    // conv+silu(+l2norm) from merged proj
    convnorm_kernel<<<(unsigned)(BT * (KD_ >> 7)),  128>>>(cproj, q_convw, qb, COL_Q, KD_,  0.08838834764831843f, T);
    convnorm_kernel<<<(unsigned)(BT * (KDR_ >> 7)), 128>>>(cproj, k_convw, kb, COL_K, KDR_, 1.0f, T);
    long nv = (long)BT * VDR_;
    conv_silu_kernel<<<(unsigned)((nv + 255) / 256), 256>>>(cproj, v_convw, vb, COL_V, VDR_, nv, T);

    long nq = (long)BT * KD_;
    decay_kernel<<<(unsigned)((nq + 255) / 256), 256>>>(graw, dt_bias, A_log, decb, nq);
    long nb = (long)BT * 64;
    beta_kernel<<<(unsigned)((nb + 255) / 256), 256>>>(cproj, betab, nb);

    // sequential microscan (packed f32x2)
    dim3 sgrid(4, H_, (unsigned)B);
    scan_kernel<<<sgrid, 128>>>(qb, kb, vb, decb, betab, dt_bias, A_log, micro, omix, T);

    // output norm + gate -> fp16, then o_proj
    post_kernel<<<(unsigned)(BT * H_), 128>>>(omix, gate, o_normw, aofh);
    tg(aofh, woh, wol, out, nullptr, BT, HID_, KD_, KD_);
}